// round 9
// baseline (speedup 1.0000x reference)
#include <cuda_runtime.h>
#include <cuda_bf16.h>
#include <mma.h>
#include <math.h>
#include <stdint.h>

using namespace nvcuda;
typedef unsigned long long ull;
typedef __nv_bfloat16 bf16;

#define NL      28000
#define DIM     200
#define NEDGES  224000
#define BATCH   4
#define T_TI    64
#define T_AB    384
#define G3      600
#define KP      448
#define Y1LD    208

// ---------------- f32x2 helpers ----------------
__device__ __forceinline__ ull dup2(float x) {
    ull r; unsigned u = __float_as_uint(x);
    asm("mov.b64 %0, {%1, %1};" : "=l"(r) : "r"(u));
    return r;
}
__device__ __forceinline__ void ffma2(ull& d, ull a, ull b) {
    asm("fma.rn.f32x2 %0, %1, %2, %0;" : "+l"(d) : "l"(a), "l"(b));
}
__device__ __forceinline__ float lo32(ull v) { return __uint_as_float((unsigned)v); }
__device__ __forceinline__ float hi32(ull v) { return __uint_as_float((unsigned)(v >> 32)); }
__device__ __forceinline__ unsigned smem_u32(const void* p) {
    unsigned a;
    asm("{ .reg .u64 t; cvta.to.shared.u64 t, %1; cvt.u32.u64 %0, t; }" : "=r"(a) : "l"(p));
    return a;
}
__device__ __forceinline__ void cpa16(unsigned s, const void* g) {
    asm volatile("cp.async.cg.shared.global [%0], [%1], 16;" :: "r"(s), "l"(g));
}

// ---------------- fp32 scratch ----------------
__host__ __device__ constexpr size_t rnd1k(size_t x) { return (x + 1023) & ~(size_t)1023; }
constexpr size_t SZ_AGG  = (size_t)NL * DIM;
constexpr size_t SZ_LF   = (size_t)NL * 2 * DIM;
constexpr size_t SZ_X0T  = (size_t)BATCH * T_TI * DIM;
constexpr size_t SZ_X0A  = (size_t)BATCH * T_AB * DIM;
constexpr size_t SZ_XL0T = (size_t)BATCH * T_TI * 2 * DIM;
constexpr size_t SZ_XL0A = (size_t)BATCH * T_AB * 2 * DIM;
constexpr size_t GXS     = (size_t)BATCH * T_AB * G3;
constexpr size_t OFF_AGG  = 0;
constexpr size_t OFF_HB   = OFF_AGG  + rnd1k(SZ_AGG);
constexpr size_t OFF_LF   = OFF_HB   + rnd1k(SZ_AGG);
constexpr size_t OFF_X0T  = OFF_LF   + rnd1k(SZ_LF);
constexpr size_t OFF_X0A  = OFF_X0T  + rnd1k(SZ_X0T);
constexpr size_t OFF_XL0T = OFF_X0A  + rnd1k(SZ_X0A);
constexpr size_t OFF_XL0A = OFF_XL0T + rnd1k(SZ_XL0T);
constexpr size_t OFF_XL1T = OFF_XL0A + rnd1k(SZ_XL0A);
constexpr size_t OFF_XL1A = OFF_XL1T + rnd1k(SZ_XL0T);
constexpr size_t OFF_GX   = OFF_XL1A + rnd1k(SZ_XL0A);
constexpr size_t OFF_WHHT = OFF_GX   + rnd1k(4 * GXS);
constexpr size_t OFF_LOG  = OFF_WHHT + rnd1k(4 * (size_t)DIM * G3);
constexpr size_t OFF_FEAT = OFF_LOG  + rnd1k((size_t)BATCH * NL * T_AB);
constexpr size_t OFF_Y1   = OFF_FEAT + rnd1k((size_t)BATCH * NL * 2 * DIM);
constexpr size_t SCR_TOTAL = OFF_Y1  + rnd1k((size_t)BATCH * NL * Y1LD);
__device__ float SCR[SCR_TOTAL];

// ---------------- bf16 hi/lo scratch ----------------
constexpr size_t NLF  = (size_t)NL * KP;
constexpr size_t NXTI = (size_t)BATCH * T_TI * KP;
constexpr size_t NXAI = (size_t)BATCH * T_AB * KP;
constexpr size_t NXTT = (size_t)BATCH * 400 * T_TI;
constexpr size_t NXTA = (size_t)BATCH * 400 * T_AB;
constexpr size_t NP   = (size_t)BATCH * NL * T_AB;
constexpr size_t NF   = (size_t)BATCH * NL * KP;
constexpr size_t NFW  = (size_t)200 * KP;
constexpr size_t B_LFH  = 0;
constexpr size_t B_LFL  = B_LFH  + NLF;
constexpr size_t B_XTIH = B_LFL  + NLF;
constexpr size_t B_XTIL = B_XTIH + NXTI;
constexpr size_t B_XAIH = B_XTIL + NXTI;
constexpr size_t B_XAIL = B_XAIH + NXAI;
constexpr size_t B_XTTH = B_XAIL + NXAI;
constexpr size_t B_XTTL = B_XTTH + NXTT;
constexpr size_t B_XTAH = B_XTTL + NXTT;
constexpr size_t B_XTAL = B_XTAH + NXTA;
constexpr size_t B_PH   = B_XTAL + NXTA;
constexpr size_t B_PL   = B_PH   + NP;
constexpr size_t B_FH   = B_PL   + NP;
constexpr size_t B_FL   = B_FH   + NF;
constexpr size_t B_FWH  = B_FL   + NF;
constexpr size_t B_FWL  = B_FWH  + NFW;
constexpr size_t BTOT   = B_FWL  + NFW;
__device__ __align__(128) bf16 BSCR[BTOT];

// ---------------- helper kernels ----------------
__global__ void gather_emb(const int* __restrict__ tok, const float* __restrict__ emb,
                           float* __restrict__ x, int total) {
    int idx = blockIdx.x * blockDim.x + threadIdx.x;
    if (idx >= total) return;
    int i = idx / DIM, f = idx - i * DIM;
    x[idx] = emb[(size_t)tok[i] * DIM + f];
}
__global__ void pack_whh(const float* __restrict__ w, float* __restrict__ wt) {
    int idx = blockIdx.x * blockDim.x + threadIdx.x;
    if (idx >= G3 * DIM) return;
    int g = idx / DIM, k = idx - g * DIM;
    wt[(size_t)(k >> 1) * (G3 * 2) + g * 2 + (k & 1)] = w[idx];
}
__global__ void copy_to_lf(const float* __restrict__ gnf, float* __restrict__ lf) {
    int idx = blockIdx.x * blockDim.x + threadIdx.x;
    if (idx >= NL * DIM) return;
    int n = idx / DIM, k = idx - n * DIM;
    lf[(size_t)n * (2 * DIM) + DIM + k] = gnf[idx];
}
__global__ void gcn_agg(const float* __restrict__ feat, const int* __restrict__ src,
                        const int* __restrict__ dst, float* __restrict__ agg) {
    long idx = (long)blockIdx.x * blockDim.x + threadIdx.x;
    const long total = (long)NEDGES * (DIM / 4);
    if (idx >= total) return;
    int e = (int)(idx / (DIM / 4));
    int q = (int)(idx - (long)e * (DIM / 4));
    const float4 v = ((const float4*)(feat + (size_t)src[e] * DIM))[q];
    float* a = agg + (size_t)dst[e] * DIM + q * 4;
    atomicAdd(a + 0, v.x); atomicAdd(a + 1, v.y);
    atomicAdd(a + 2, v.z); atomicAdd(a + 3, v.w);
}
__global__ void f2b2_pad(const float* __restrict__ in, bf16* __restrict__ oh,
                         bf16* __restrict__ ol, long rows, int cin, int cout) {
    long idx = (long)blockIdx.x * blockDim.x + threadIdx.x;
    if (idx >= rows * cout) return;
    long r = idx / cout; int c = (int)(idx - r * cout);
    float x = (c < cin) ? in[r * cin + c] : 0.f;
    bf16 h = __float2bfloat16(x);
    oh[idx] = h;
    ol[idx] = __float2bfloat16(x - __bfloat162float(h));
}
__global__ void build_xt(const float* __restrict__ x, bf16* __restrict__ oh,
                         bf16* __restrict__ ol, int T) {
    long idx = (long)blockIdx.x * blockDim.x + threadIdx.x;
    long total = (long)BATCH * 400 * T;
    if (idx >= total) return;
    int t = (int)(idx % T);
    int d = (int)((idx / T) % 400);
    int b = (int)(idx / ((long)400 * T));
    float v = x[((long)b * T + t) * 400 + d];
    bf16 h = __float2bfloat16(v);
    oh[idx] = h;
    ol[idx] = __float2bfloat16(v - __bfloat162float(h));
}
__global__ void softmax_pb(const float* __restrict__ logits, bf16* __restrict__ ph,
                           bf16* __restrict__ pl, int rows, int T) {
    int gw = (blockIdx.x * blockDim.x + threadIdx.x) >> 5;
    int lane = threadIdx.x & 31;
    if (gw >= rows) return;
    const float* p = logits + (size_t)gw * T;
    float v[12];
    int cnt = 0;
    float mx = -1e30f;
    for (int i = lane; i < T; i += 32) { float x = p[i]; v[cnt++] = x; mx = fmaxf(mx, x); }
    #pragma unroll
    for (int o = 16; o; o >>= 1) mx = fmaxf(mx, __shfl_xor_sync(0xffffffffu, mx, o));
    float s = 0.f;
    for (int c = 0; c < cnt; c++) { v[c] = expf(v[c] - mx); s += v[c]; }
    #pragma unroll
    for (int o = 16; o; o >>= 1) s += __shfl_xor_sync(0xffffffffu, s, o);
    float inv = 1.f / s;
    cnt = 0;
    for (int i = lane; i < T; i += 32) {
        float pv = v[cnt++] * inv;
        bf16 h = __float2bfloat16(pv);
        ph[(size_t)gw * T + i] = h;
        pl[(size_t)gw * T + i] = __float2bfloat16(pv - __bfloat162float(h));
    }
}
__global__ void bias_leaky(float* __restrict__ y, const float* __restrict__ b, long rows) {
    long idx = (long)blockIdx.x * blockDim.x + threadIdx.x;
    if (idx >= rows * 200) return;
    long r = idx / 200; int c = (int)(idx - r * 200);
    float v = y[r * Y1LD + c] + b[c];
    y[r * Y1LD + c] = v > 0.f ? v : 0.2f * v;
}
__global__ void fc2_kernel(const float* __restrict__ y1, const float* __restrict__ w2,
                           const float* __restrict__ b2, float* __restrict__ out, int M) {
    int gw = (blockIdx.x * blockDim.x + threadIdx.x) >> 5;
    int lane = threadIdx.x & 31;
    if (gw >= M) return;
    const float* row = y1 + (size_t)gw * Y1LD;
    float s = 0.f;
    for (int k = lane; k < DIM; k += 32) s += row[k] * w2[k];
    #pragma unroll
    for (int o = 16; o; o >>= 1) s += __shfl_xor_sync(0xffffffffu, s, o);
    if (lane == 0) {
        float v = s + b2[0];
        out[gw] = v > 0.f ? v : 0.2f * v;
    }
}

// ---------------- fp32 NT GEMM (GCN + gx) ----------------
__global__ void __launch_bounds__(256, 2) gemm_nt128(
    const float* __restrict__ A, const float* __restrict__ Bm,
    const float* __restrict__ bias, float* __restrict__ C,
    int M, int N, int K, int ldc, int act)
{
    __shared__ __align__(16) float As[8][128];
    __shared__ __align__(16) float Bs[8][128];
    int tid = threadIdx.x;
    int m0 = blockIdx.y * 128, n0 = blockIdx.x * 128;
    int ty = tid >> 4, tx = tid & 15;
    int ar = tid >> 1, ak = (tid & 1) * 4;
    int am = m0 + ar; if (am >= M) am = M - 1;
    int bn = n0 + ar; if (bn >= N) bn = N - 1;
    const float* Ap = A + (size_t)am * K + ak;
    const float* Bp = Bm + (size_t)bn * K + ak;
    ull acc[4][8];
    #pragma unroll
    for (int i = 0; i < 4; i++)
        #pragma unroll
        for (int j = 0; j < 8; j++) acc[i][j] = 0ull;
    float4 apf = *(const float4*)Ap;
    float4 bpf = *(const float4*)Bp;
    for (int k0 = 0; k0 < K; k0 += 8) {
        As[ak + 0][ar] = apf.x; As[ak + 1][ar] = apf.y;
        As[ak + 2][ar] = apf.z; As[ak + 3][ar] = apf.w;
        Bs[ak + 0][ar] = bpf.x; Bs[ak + 1][ar] = bpf.y;
        Bs[ak + 2][ar] = bpf.z; Bs[ak + 3][ar] = bpf.w;
        __syncthreads();
        if (k0 + 8 < K) {
            apf = *(const float4*)(Ap + k0 + 8);
            bpf = *(const float4*)(Bp + k0 + 8);
        }
        #pragma unroll
        for (int kk = 0; kk < 8; kk++) {
            ulonglong2 a01 = *(const ulonglong2*)&As[kk][ty * 8];
            ulonglong2 a23 = *(const ulonglong2*)&As[kk][ty * 8 + 4];
            float4 bv0 = *(const float4*)&Bs[kk][tx * 8];
            float4 bv1 = *(const float4*)&Bs[kk][tx * 8 + 4];
            ull bd[8];
            bd[0] = dup2(bv0.x); bd[1] = dup2(bv0.y); bd[2] = dup2(bv0.z); bd[3] = dup2(bv0.w);
            bd[4] = dup2(bv1.x); bd[5] = dup2(bv1.y); bd[6] = dup2(bv1.z); bd[7] = dup2(bv1.w);
            ull av[4] = {a01.x, a01.y, a23.x, a23.y};
            #pragma unroll
            for (int i = 0; i < 4; i++)
                #pragma unroll
                for (int j = 0; j < 8; j++) ffma2(acc[i][j], av[i], bd[j]);
        }
        __syncthreads();
    }
    #pragma unroll
    for (int i = 0; i < 4; i++) {
        int gm0 = m0 + ty * 8 + 2 * i;
        #pragma unroll
        for (int j = 0; j < 8; j++) {
            int gn = n0 + tx * 8 + j;
            if (gn >= N) continue;
            float b = bias ? bias[gn] : 0.f;
            float v0 = lo32(acc[i][j]) + b;
            float v1 = hi32(acc[i][j]) + b;
            if (act == 1) { v0 = fmaxf(v0, 0.f); v1 = fmaxf(v1, 0.f); }
            if (gm0 < M)     C[(size_t)gm0 * ldc + gn] = v0;
            if (gm0 + 1 < M) C[(size_t)(gm0 + 1) * ldc + gn] = v1;
        }
    }
}

// ---------------- wmma bf16 hi/lo NT GEMM, 2-stage cp.async pipeline ----------------
#define SP 40
constexpr int TILE_E  = 128 * SP;          // elems per sub-tile
constexpr int STAGE_E = 4 * TILE_E;        // Ah,Al,Bh,Bl
constexpr unsigned WMMA_SMEM = 2u * STAGE_E * 2u;  // bytes (81920)

__global__ void __launch_bounds__(256) wmma_nt(
    const bf16* __restrict__ Ah, const bf16* __restrict__ Al,
    const bf16* __restrict__ Bh, const bf16* __restrict__ Bl,
    float* __restrict__ C,
    int M, int N, int K, int lda, int ldb, int Brows, int ldc,
    size_t sA, size_t sB, size_t sC, int accInit)
{
    extern __shared__ __align__(16) bf16 sm[];
    Ah += sA * blockIdx.z; Al += sA * blockIdx.z;
    Bh += sB * blockIdx.z; Bl += sB * blockIdx.z;
    C  += sC * blockIdx.z;
    int tid = threadIdx.x, wid = tid >> 5;
    int m0 = blockIdx.y * 128, n0 = blockIdx.x * 128;
    int wm = wid >> 2, wn = wid & 3;

    wmma::fragment<wmma::accumulator, 16, 16, 16, float> acc[4][2];
    #pragma unroll
    for (int i = 0; i < 4; i++)
        #pragma unroll
        for (int j = 0; j < 2; j++) {
            int gm = m0 + wm * 64 + i * 16, gn = n0 + wn * 32 + j * 16;
            if (accInit && gm + 16 <= M && gn + 16 <= N)
                wmma::load_matrix_sync(acc[i][j], C + (size_t)gm * ldc + gn, ldc, wmma::mem_row_major);
            else
                wmma::fill_fragment(acc[i][j], 0.f);
        }

    int r = tid >> 1, col = (tid & 1) * 16;
    int ga = m0 + r; if (ga > M - 1) ga = M - 1;
    int gb = n0 + r; if (gb > Brows - 1) gb = Brows - 1;
    const bf16* pAh = Ah + (size_t)ga * lda + col;
    const bf16* pAl = Al + (size_t)ga * lda + col;
    const bf16* pBh = Bh + (size_t)gb * ldb + col;
    const bf16* pBl = Bl + (size_t)gb * ldb + col;
    unsigned sb = smem_u32(sm);
    unsigned doff = (unsigned)(r * SP + col) * 2u;
    const unsigned TB = (unsigned)TILE_E * 2u;   // sub-tile bytes
    const unsigned SB = (unsigned)STAGE_E * 2u;  // stage bytes

    int S = K / 32;
    // prologue: stage 0
    {
        unsigned st = sb;
        cpa16(st + 0 * TB + doff,      pAh);      cpa16(st + 0 * TB + doff + 16, pAh + 8);
        cpa16(st + 1 * TB + doff,      pAl);      cpa16(st + 1 * TB + doff + 16, pAl + 8);
        cpa16(st + 2 * TB + doff,      pBh);      cpa16(st + 2 * TB + doff + 16, pBh + 8);
        cpa16(st + 3 * TB + doff,      pBl);      cpa16(st + 3 * TB + doff + 16, pBl + 8);
        asm volatile("cp.async.commit_group;" ::: "memory");
    }
    for (int s = 0; s < S; s++) {
        if (s + 1 < S) {
            unsigned st = sb + (unsigned)((s + 1) & 1) * SB;
            int k0 = (s + 1) * 32;
            cpa16(st + 0 * TB + doff,      pAh + k0);  cpa16(st + 0 * TB + doff + 16, pAh + k0 + 8);
            cpa16(st + 1 * TB + doff,      pAl + k0);  cpa16(st + 1 * TB + doff + 16, pAl + k0 + 8);
            cpa16(st + 2 * TB + doff,      pBh + k0);  cpa16(st + 2 * TB + doff + 16, pBh + k0 + 8);
            cpa16(st + 3 * TB + doff,      pBl + k0);  cpa16(st + 3 * TB + doff + 16, pBl + k0 + 8);
            asm volatile("cp.async.commit_group;" ::: "memory");
            asm volatile("cp.async.wait_group 1;" ::: "memory");
        } else {
            asm volatile("cp.async.wait_group 0;" ::: "memory");
        }
        __syncthreads();
        const bf16* stA_h = sm + (size_t)(s & 1) * STAGE_E;
        const bf16* stA_l = stA_h + TILE_E;
        const bf16* stB_h = stA_h + 2 * TILE_E;
        const bf16* stB_l = stA_h + 3 * TILE_E;
        #pragma unroll
        for (int ks = 0; ks < 32; ks += 16) {
            wmma::fragment<wmma::matrix_b, 16, 16, 16, bf16, wmma::col_major> bh[2], bl[2];
            #pragma unroll
            for (int j = 0; j < 2; j++) {
                wmma::load_matrix_sync(bh[j], stB_h + (wn * 32 + j * 16) * SP + ks, SP);
                wmma::load_matrix_sync(bl[j], stB_l + (wn * 32 + j * 16) * SP + ks, SP);
            }
            #pragma unroll
            for (int i = 0; i < 4; i++) {
                wmma::fragment<wmma::matrix_a, 16, 16, 16, bf16, wmma::row_major> ah, al;
                wmma::load_matrix_sync(ah, stA_h + (wm * 64 + i * 16) * SP + ks, SP);
                wmma::load_matrix_sync(al, stA_l + (wm * 64 + i * 16) * SP + ks, SP);
                #pragma unroll
                for (int j = 0; j < 2; j++) {
                    wmma::mma_sync(acc[i][j], ah, bh[j], acc[i][j]);
                    wmma::mma_sync(acc[i][j], ah, bl[j], acc[i][j]);
                    wmma::mma_sync(acc[i][j], al, bh[j], acc[i][j]);
                }
            }
        }
        __syncthreads();
    }
    #pragma unroll
    for (int i = 0; i < 4; i++)
        #pragma unroll
        for (int j = 0; j < 2; j++) {
            int gm = m0 + wm * 64 + i * 16, gn = n0 + wn * 32 + j * 16;
            if (gm + 16 <= M && gn + 16 <= N)
                wmma::store_matrix_sync(C + (size_t)gm * ldc + gn, acc[i][j], ldc, wmma::mem_row_major);
        }
}

// ---------------- GRU scan ----------------
__global__ void __launch_bounds__(640) gru_scan(
    const float* __restrict__ gxbase,
    const float* __restrict__ whht_f, const float* __restrict__ whht_b,
    const float* __restrict__ bhh_f,  const float* __restrict__ bhh_b,
    const int* __restrict__ lenT, const int* __restrict__ lenA,
    float* __restrict__ xoutT, float* __restrict__ xoutA)
{
    int b = blockIdx.x, d = blockIdx.y, br = blockIdx.z;
    int T = br ? T_AB : T_TI;
    int len = (br ? lenA : lenT)[b];
    if (len < 0) len = 0;
    if (len > T) len = T;
    const float* gx = gxbase + (size_t)(br * 2 + d) * GXS + (size_t)b * T * G3;
    float* xout = (br ? xoutA : xoutT) + (size_t)b * T * (2 * DIM) + d * DIM;
    const float* whht = d ? whht_b : whht_f;
    const float* bhh  = d ? bhh_b  : bhh_f;
    __shared__ __align__(16) float h_s[DIM];
    __shared__ float gh_s[G3];
    int tid = threadIdx.x;
    if (tid < DIM) h_s[tid] = 0.f;
    float bh = (tid < G3) ? bhh[tid] : 0.f;
    const float* wcol = whht + tid * 2;
    __syncthreads();
    for (int s = 0; s < len; s++) {
        int t = d ? (len - 1 - s) : s;
        if (tid < G3) {
            const ull* h2 = (const ull*)h_s;
            ull a0 = 0ull, a1 = 0ull, a2 = 0ull, a3 = 0ull;
            #pragma unroll 5
            for (int p = 0; p < DIM / 2; p += 4) {
                ffma2(a0, h2[p + 0], *(const ull*)(wcol + (size_t)(p + 0) * (2 * G3)));
                ffma2(a1, h2[p + 1], *(const ull*)(wcol + (size_t)(p + 1) * (2 * G3)));
                ffma2(a2, h2[p + 2], *(const ull*)(wcol + (size_t)(p + 2) * (2 * G3)));
                ffma2(a3, h2[p + 3], *(const ull*)(wcol + (size_t)(p + 3) * (2 * G3)));
            }
            gh_s[tid] = bh + lo32(a0) + hi32(a0) + lo32(a1) + hi32(a1)
                           + lo32(a2) + hi32(a2) + lo32(a3) + hi32(a3);
        }
        __syncthreads();
        if (tid < DIM) {
            const float* g = gx + (size_t)t * G3;
            float r = 1.f / (1.f + expf(-(g[tid]           + gh_s[tid])));
            float z = 1.f / (1.f + expf(-(g[DIM + tid]     + gh_s[DIM + tid])));
            float n = tanhf(g[2 * DIM + tid] + r * gh_s[2 * DIM + tid]);
            float hn = (1.f - z) * n + z * h_s[tid];
            h_s[tid] = hn;
            xout[(size_t)t * (2 * DIM) + tid] = hn;
        }
        __syncthreads();
    }
}

// ---------------- launcher ----------------
static inline int ceildiv(int a, int b) { return (a + b - 1) / b; }

extern "C" void kernel_launch(void* const* d_in, const int* in_sizes, int n_in,
                              void* d_out, int out_size) {
    (void)in_sizes; (void)n_in; (void)out_size;
    const int*   in_ab   = (const int*)d_in[0];
    const int*   in_ti   = (const int*)d_in[1];
    const int*   ab_len  = (const int*)d_in[2];
    const int*   ti_len  = (const int*)d_in[3];
    const int*   esrc    = (const int*)d_in[4];
    const int*   edst    = (const int*)d_in[5];
    const float* gnf     = (const float*)d_in[6];
    const float* emb     = (const float*)d_in[7];
    const float* wih_l0f = (const float*)d_in[8];
    const float* whh_l0f = (const float*)d_in[9];
    const float* bih_l0f = (const float*)d_in[10];
    const float* bhh_l0f = (const float*)d_in[11];
    const float* wih_l0b = (const float*)d_in[12];
    const float* whh_l0b = (const float*)d_in[13];
    const float* bih_l0b = (const float*)d_in[14];
    const float* bhh_l0b = (const float*)d_in[15];
    const float* wih_l1f = (const float*)d_in[16];
    const float* whh_l1f = (const float*)d_in[17];
    const float* bih_l1f = (const float*)d_in[18];
    const float* bhh_l1f = (const float*)d_in[19];
    const float* wih_l1b = (const float*)d_in[20];
    const float* whh_l1b = (const float*)d_in[21];
    const float* bih_l1b = (const float*)d_in[22];
    const float* bhh_l1b = (const float*)d_in[23];
    const float* gcn_w1  = (const float*)d_in[24];
    const float* gcn_b1  = (const float*)d_in[25];
    const float* gcn_w2  = (const float*)d_in[26];
    const float* gcn_b2  = (const float*)d_in[27];
    const float* fc1_w   = (const float*)d_in[28];
    const float* fc1_b   = (const float*)d_in[29];
    const float* fc2_w   = (const float*)d_in[30];
    const float* fc2_b   = (const float*)d_in[31];
    float* out = (float*)d_out;

    cudaFuncSetAttribute(wmma_nt, cudaFuncAttributeMaxDynamicSharedMemorySize, WMMA_SMEM);

    float* S = nullptr;  cudaGetSymbolAddress((void**)&S, SCR);
    bf16* Bb = nullptr;  cudaGetSymbolAddress((void**)&Bb, BSCR);
    float* AGG  = S + OFF_AGG;
    float* HB   = S + OFF_HB;
    float* LF   = S + OFF_LF;
    float* X0T  = S + OFF_X0T;
    float* X0A  = S + OFF_X0A;
    float* XL0T = S + OFF_XL0T;
    float* XL0A = S + OFF_XL0A;
    float* XL1T = S + OFF_XL1T;
    float* XL1A = S + OFF_XL1A;
    float* GX   = S + OFF_GX;
    float* WHHT = S + OFF_WHHT;
    float* LOG  = S + OFF_LOG;
    float* FEAT = S + OFF_FEAT;
    float* Y1   = S + OFF_Y1;

    cudaMemsetAsync(AGG,  0, SZ_AGG  * 4);
    cudaMemsetAsync(XL0T, 0, SZ_XL0T * 4);
    cudaMemsetAsync(XL0A, 0, SZ_XL0A * 4);
    cudaMemsetAsync(XL1T, 0, SZ_XL0T * 4);
    cudaMemsetAsync(XL1A, 0, SZ_XL0A * 4);

    {
        int blks = ceildiv(G3 * DIM, 256);
        pack_whh<<<blks, 256>>>(whh_l0f, WHHT + 0 * (size_t)DIM * G3);
        pack_whh<<<blks, 256>>>(whh_l0b, WHHT + 1 * (size_t)DIM * G3);
        pack_whh<<<blks, 256>>>(whh_l1f, WHHT + 2 * (size_t)DIM * G3);
        pack_whh<<<blks, 256>>>(whh_l1b, WHHT + 3 * (size_t)DIM * G3);
    }
    gather_emb<<<ceildiv(BATCH * T_TI * DIM, 256), 256>>>(in_ti, emb, X0T, BATCH * T_TI * DIM);
    gather_emb<<<ceildiv(BATCH * T_AB * DIM, 256), 256>>>(in_ab, emb, X0A, BATCH * T_AB * DIM);
    f2b2_pad<<<ceildiv(200 * KP, 256), 256>>>(fc1_w, Bb + B_FWH, Bb + B_FWL, 200, 400, KP);

    // ---- GCN ----
    {
        long total = (long)NEDGES * (DIM / 4);
        int blks = (int)((total + 255) / 256);
        gcn_agg<<<blks, 256>>>(gnf, esrc, edst, AGG);
        dim3 g1(ceildiv(DIM, 128), ceildiv(NL, 128), 1);
        gemm_nt128<<<g1, 256>>>(AGG, gcn_w1, gcn_b1, HB, NL, DIM, DIM, DIM, 1);
        cudaMemsetAsync(AGG, 0, SZ_AGG * 4);
        gcn_agg<<<blks, 256>>>(HB, esrc, edst, AGG);
        gemm_nt128<<<g1, 256>>>(AGG, gcn_w2, gcn_b2, LF, NL, DIM, DIM, 2 * DIM, 0);
        copy_to_lf<<<ceildiv(NL * DIM, 256), 256>>>(gnf, LF);
        f2b2_pad<<<(int)(((long)NL * KP + 255) / 256), 256>>>(LF, Bb + B_LFH, Bb + B_LFL, NL, 400, KP);
    }

    // ---- GRU layer 0 ----
    {
        dim3 gT(ceildiv(G3, 128), ceildiv(BATCH * T_TI, 128), 1);
        dim3 gA(ceildiv(G3, 128), ceildiv(BATCH * T_AB, 128), 1);
        gemm_nt128<<<gT, 256>>>(X0T, wih_l0f, bih_l0f, GX + 0 * GXS, BATCH * T_TI, G3, DIM, G3, 0);
        gemm_nt128<<<gT, 256>>>(X0T, wih_l0b, bih_l0b, GX + 1 * GXS, BATCH * T_TI, G3, DIM, G3, 0);
        gemm_nt128<<<gA, 256>>>(X0A, wih_l0f, bih_l0f, GX + 2 * GXS, BATCH * T_AB, G3, DIM, G3, 0);
        gemm_nt128<<<gA, 256>>>(X0A, wih_l0b, bih_l0b, GX + 3 * GXS, BATCH * T_AB, G3, DIM, G3, 0);
        dim3 gs(BATCH, 2, 2);
        gru_scan<<<gs, 640>>>(GX, WHHT + 0 * (size_t)DIM * G3, WHHT + 1 * (size_t)DIM * G3,
                              bhh_l0f, bhh_l0b, ti_len, ab_len, XL0T, XL0A);
    }
    // ---- GRU layer 1 ----
    {
        dim3 gT(ceildiv(G3, 128), ceildiv(BATCH * T_TI, 128), 1);
        dim3 gA(ceildiv(G3, 128), ceildiv(BATCH * T_AB, 128), 1);
        gemm_nt128<<<gT, 256>>>(XL0T, wih_l1f, bih_l1f, GX + 0 * GXS, BATCH * T_TI, G3, 2 * DIM, G3, 0);
        gemm_nt128<<<gT, 256>>>(XL0T, wih_l1b, bih_l1b, GX + 1 * GXS, BATCH * T_TI, G3, 2 * DIM, G3, 0);
        gemm_nt128<<<gA, 256>>>(XL0A, wih_l1f, bih_l1f, GX + 2 * GXS, BATCH * T_AB, G3, 2 * DIM, G3, 0);
        gemm_nt128<<<gA, 256>>>(XL0A, wih_l1b, bih_l1b, GX + 3 * GXS, BATCH * T_AB, G3, 2 * DIM, G3, 0);
        dim3 gs(BATCH, 2, 2);
        gru_scan<<<gs, 640>>>(GX, WHHT + 2 * (size_t)DIM * G3, WHHT + 3 * (size_t)DIM * G3,
                              bhh_l1f, bhh_l1b, ti_len, ab_len, XL1T, XL1A);
    }

    // ---- bf16 conversions of GRU outputs ----
    f2b2_pad<<<ceildiv(BATCH * T_TI * KP, 256), 256>>>(XL1T, Bb + B_XTIH, Bb + B_XTIL,
                                                        BATCH * T_TI, 400, KP);
    f2b2_pad<<<ceildiv(BATCH * T_AB * KP, 256), 256>>>(XL1A, Bb + B_XAIH, Bb + B_XAIL,
                                                        BATCH * T_AB, 400, KP);
    build_xt<<<ceildiv(BATCH * 400 * T_TI, 256), 256>>>(XL1T, Bb + B_XTTH, Bb + B_XTTL, T_TI);
    build_xt<<<ceildiv(BATCH * 400 * T_AB, 256), 256>>>(XL1A, Bb + B_XTAH, Bb + B_XTAL, T_AB);

    int gy = ceildiv(NL, 128);
    // ---- title attention ----
    {
        dim3 gl(1, gy, BATCH);
        wmma_nt<<<gl, 256, WMMA_SMEM>>>(Bb + B_LFH, Bb + B_LFL, Bb + B_XTIH, Bb + B_XTIL, LOG,
                             NL, T_TI, KP, KP, KP, T_TI, T_TI,
                             0, (size_t)T_TI * KP, (size_t)NL * T_TI, 0);
        softmax_pb<<<ceildiv(BATCH * NL, 8), 256>>>(LOG, Bb + B_PH, Bb + B_PL, BATCH * NL, T_TI);
        dim3 gw(ceildiv(400, 128), gy, BATCH);
        wmma_nt<<<gw, 256, WMMA_SMEM>>>(Bb + B_PH, Bb + B_PL, Bb + B_XTTH, Bb + B_XTTL, FEAT,
                             NL, 400, T_TI, T_TI, T_TI, 400, 400,
                             (size_t)NL * T_TI, (size_t)400 * T_TI, (size_t)NL * 400, 0);
    }
    // ---- abstract attention (accumulates into FEAT) ----
    {
        dim3 gl(ceildiv(T_AB, 128), gy, BATCH);
        wmma_nt<<<gl, 256, WMMA_SMEM>>>(Bb + B_LFH, Bb + B_LFL, Bb + B_XAIH, Bb + B_XAIL, LOG,
                             NL, T_AB, KP, KP, KP, T_AB, T_AB,
                             0, (size_t)T_AB * KP, (size_t)NL * T_AB, 0);
        softmax_pb<<<ceildiv(BATCH * NL, 8), 256>>>(LOG, Bb + B_PH, Bb + B_PL, BATCH * NL, T_AB);
        dim3 gw(ceildiv(400, 128), gy, BATCH);
        wmma_nt<<<gw, 256, WMMA_SMEM>>>(Bb + B_PH, Bb + B_PL, Bb + B_XTAH, Bb + B_XTAL, FEAT,
                             NL, 400, T_AB, T_AB, T_AB, 400, 400,
                             (size_t)NL * T_AB, (size_t)400 * T_AB, (size_t)NL * 400, 1);
    }

    // ---- output head ----
    {
        f2b2_pad<<<(int)(((long)BATCH * NL * KP + 255) / 256), 256>>>(
            FEAT, Bb + B_FH, Bb + B_FL, (long)BATCH * NL, 400, KP);
        dim3 gf(2, ceildiv(BATCH * NL, 128), 1);
        wmma_nt<<<gf, 256, WMMA_SMEM>>>(Bb + B_FH, Bb + B_FL, Bb + B_FWH, Bb + B_FWL, Y1,
                             BATCH * NL, Y1LD, KP, KP, KP, 200, Y1LD,
                             0, 0, 0, 0);
        bias_leaky<<<(int)(((long)BATCH * NL * 200 + 255) / 256), 256>>>(Y1, fc1_b, (long)BATCH * NL);
        fc2_kernel<<<ceildiv(BATCH * NL, 8), 256>>>(Y1, fc2_w, fc2_b, out, BATCH * NL);
    }
}

// round 10
// speedup vs baseline: 1.0585x; 1.0585x over previous
#include <cuda_runtime.h>
#include <cuda_bf16.h>
#include <mma.h>
#include <math.h>
#include <stdint.h>

using namespace nvcuda;
typedef unsigned long long ull;
typedef __nv_bfloat16 bf16;

#define NL      28000
#define DIM     200
#define NEDGES  224000
#define BATCH   4
#define T_TI    64
#define T_AB    384
#define G3      600
#define KP      416
#define Y1LD    208

// ---------------- f32x2 helpers ----------------
__device__ __forceinline__ ull dup2(float x) {
    ull r; unsigned u = __float_as_uint(x);
    asm("mov.b64 %0, {%1, %1};" : "=l"(r) : "r"(u));
    return r;
}
__device__ __forceinline__ void ffma2(ull& d, ull a, ull b) {
    asm("fma.rn.f32x2 %0, %1, %2, %0;" : "+l"(d) : "l"(a), "l"(b));
}
__device__ __forceinline__ float lo32(ull v) { return __uint_as_float((unsigned)v); }
__device__ __forceinline__ float hi32(ull v) { return __uint_as_float((unsigned)(v >> 32)); }

// ---------------- fp32 scratch ----------------
__host__ __device__ constexpr size_t rnd1k(size_t x) { return (x + 1023) & ~(size_t)1023; }
constexpr size_t SZ_AGG  = (size_t)NL * DIM;
constexpr size_t SZ_LF   = (size_t)NL * 2 * DIM;
constexpr size_t SZ_X0T  = (size_t)BATCH * T_TI * DIM;
constexpr size_t SZ_X0A  = (size_t)BATCH * T_AB * DIM;
constexpr size_t SZ_XL0T = (size_t)BATCH * T_TI * 2 * DIM;
constexpr size_t SZ_XL0A = (size_t)BATCH * T_AB * 2 * DIM;
constexpr size_t GXS     = (size_t)BATCH * T_AB * G3;
constexpr size_t OFF_AGG  = 0;
constexpr size_t OFF_HB   = OFF_AGG  + rnd1k(SZ_AGG);
constexpr size_t OFF_LF   = OFF_HB   + rnd1k(SZ_AGG);
constexpr size_t OFF_X0T  = OFF_LF   + rnd1k(SZ_LF);
constexpr size_t OFF_X0A  = OFF_X0T  + rnd1k(SZ_X0T);
constexpr size_t OFF_XL0T = OFF_X0A  + rnd1k(SZ_X0A);
constexpr size_t OFF_XL0A = OFF_XL0T + rnd1k(SZ_XL0T);
constexpr size_t OFF_XL1T = OFF_XL0A + rnd1k(SZ_XL0A);
constexpr size_t OFF_XL1A = OFF_XL1T + rnd1k(SZ_XL0T);
constexpr size_t OFF_GX   = OFF_XL1A + rnd1k(SZ_XL0A);
constexpr size_t OFF_WHHT = OFF_GX   + rnd1k(4 * GXS);
constexpr size_t OFF_LOG  = OFF_WHHT + rnd1k(4 * (size_t)DIM * G3);
constexpr size_t OFF_FEAT = OFF_LOG  + rnd1k((size_t)BATCH * NL * T_AB);
constexpr size_t OFF_Y1   = OFF_FEAT + rnd1k((size_t)BATCH * NL * 2 * DIM);
constexpr size_t SCR_TOTAL = OFF_Y1  + rnd1k((size_t)BATCH * NL * Y1LD);
__device__ float SCR[SCR_TOTAL];

// ---------------- bf16 hi/lo scratch ----------------
constexpr size_t NLF  = (size_t)NL * KP;
constexpr size_t NXTI = (size_t)BATCH * T_TI * KP;
constexpr size_t NXAI = (size_t)BATCH * T_AB * KP;
constexpr size_t NXTT = (size_t)BATCH * 400 * T_TI;
constexpr size_t NXTA = (size_t)BATCH * 400 * T_AB;
constexpr size_t NP   = (size_t)BATCH * NL * T_AB;
constexpr size_t NF   = (size_t)BATCH * NL * KP;
constexpr size_t NFW  = (size_t)200 * KP;
constexpr size_t B_LFH  = 0;
constexpr size_t B_LFL  = B_LFH  + NLF;
constexpr size_t B_XTIH = B_LFL  + NLF;
constexpr size_t B_XTIL = B_XTIH + NXTI;
constexpr size_t B_XAIH = B_XTIL + NXTI;
constexpr size_t B_XAIL = B_XAIH + NXAI;
constexpr size_t B_XTTH = B_XAIL + NXAI;
constexpr size_t B_XTTL = B_XTTH + NXTT;
constexpr size_t B_XTAH = B_XTTL + NXTT;
constexpr size_t B_XTAL = B_XTAH + NXTA;
constexpr size_t B_PH   = B_XTAL + NXTA;
constexpr size_t B_PL   = B_PH   + NP;
constexpr size_t B_FH   = B_PL   + NP;
constexpr size_t B_FL   = B_FH   + NF;
constexpr size_t B_FWH  = B_FL   + NF;
constexpr size_t B_FWL  = B_FWH  + NFW;
constexpr size_t BTOT   = B_FWL  + NFW;
__device__ __align__(128) bf16 BSCR[BTOT];

// ---------------- helper kernels ----------------
__global__ void gather_emb(const int* __restrict__ tok, const float* __restrict__ emb,
                           float* __restrict__ x, int total) {
    int idx = blockIdx.x * blockDim.x + threadIdx.x;
    if (idx >= total) return;
    int i = idx / DIM, f = idx - i * DIM;
    x[idx] = emb[(size_t)tok[i] * DIM + f];
}
__global__ void pack_whh(const float* __restrict__ w, float* __restrict__ wt) {
    int idx = blockIdx.x * blockDim.x + threadIdx.x;
    if (idx >= G3 * DIM) return;
    int g = idx / DIM, k = idx - g * DIM;
    wt[(size_t)(k >> 1) * (G3 * 2) + g * 2 + (k & 1)] = w[idx];
}
__global__ void copy_to_lf(const float* __restrict__ gnf, float* __restrict__ lf) {
    int idx = blockIdx.x * blockDim.x + threadIdx.x;
    if (idx >= NL * DIM) return;
    int n = idx / DIM, k = idx - n * DIM;
    lf[(size_t)n * (2 * DIM) + DIM + k] = gnf[idx];
}
__global__ void gcn_agg(const float* __restrict__ feat, const int* __restrict__ src,
                        const int* __restrict__ dst, float* __restrict__ agg) {
    long idx = (long)blockIdx.x * blockDim.x + threadIdx.x;
    const long total = (long)NEDGES * (DIM / 4);
    if (idx >= total) return;
    int e = (int)(idx / (DIM / 4));
    int q = (int)(idx - (long)e * (DIM / 4));
    const float4 v = ((const float4*)(feat + (size_t)src[e] * DIM))[q];
    float* a = agg + (size_t)dst[e] * DIM + q * 4;
    atomicAdd(a + 0, v.x); atomicAdd(a + 1, v.y);
    atomicAdd(a + 2, v.z); atomicAdd(a + 3, v.w);
}
__global__ void f2b2_pad(const float* __restrict__ in, bf16* __restrict__ oh,
                         bf16* __restrict__ ol, long rows, int cin, int cout) {
    long idx = (long)blockIdx.x * blockDim.x + threadIdx.x;
    if (idx >= rows * cout) return;
    long r = idx / cout; int c = (int)(idx - r * cout);
    float x = (c < cin) ? in[r * cin + c] : 0.f;
    bf16 h = __float2bfloat16(x);
    oh[idx] = h;
    ol[idx] = __float2bfloat16(x - __bfloat162float(h));
}
__global__ void build_xt(const float* __restrict__ x, bf16* __restrict__ oh,
                         bf16* __restrict__ ol, int T) {
    long idx = (long)blockIdx.x * blockDim.x + threadIdx.x;
    long total = (long)BATCH * 400 * T;
    if (idx >= total) return;
    int t = (int)(idx % T);
    int d = (int)((idx / T) % 400);
    int b = (int)(idx / ((long)400 * T));
    float v = x[((long)b * T + t) * 400 + d];
    bf16 h = __float2bfloat16(v);
    oh[idx] = h;
    ol[idx] = __float2bfloat16(v - __bfloat162float(h));
}
__global__ void softmax_pb(const float* __restrict__ logits, bf16* __restrict__ ph,
                           bf16* __restrict__ pl, int rows, int T) {
    int gw = (blockIdx.x * blockDim.x + threadIdx.x) >> 5;
    int lane = threadIdx.x & 31;
    if (gw >= rows) return;
    const float* p = logits + (size_t)gw * T;
    float v[12];
    int cnt = 0;
    float mx = -1e30f;
    for (int i = lane; i < T; i += 32) { float x = p[i]; v[cnt++] = x; mx = fmaxf(mx, x); }
    #pragma unroll
    for (int o = 16; o; o >>= 1) mx = fmaxf(mx, __shfl_xor_sync(0xffffffffu, mx, o));
    float s = 0.f;
    for (int c = 0; c < cnt; c++) { v[c] = expf(v[c] - mx); s += v[c]; }
    #pragma unroll
    for (int o = 16; o; o >>= 1) s += __shfl_xor_sync(0xffffffffu, s, o);
    float inv = 1.f / s;
    cnt = 0;
    for (int i = lane; i < T; i += 32) {
        float pv = v[cnt++] * inv;
        bf16 h = __float2bfloat16(pv);
        ph[(size_t)gw * T + i] = h;
        pl[(size_t)gw * T + i] = __float2bfloat16(pv - __bfloat162float(h));
    }
}
__global__ void bias_leaky(float* __restrict__ y, const float* __restrict__ b, long rows) {
    long idx = (long)blockIdx.x * blockDim.x + threadIdx.x;
    if (idx >= rows * 200) return;
    long r = idx / 200; int c = (int)(idx - r * 200);
    float v = y[r * Y1LD + c] + b[c];
    y[r * Y1LD + c] = v > 0.f ? v : 0.2f * v;
}
__global__ void fc2_kernel(const float* __restrict__ y1, const float* __restrict__ w2,
                           const float* __restrict__ b2, float* __restrict__ out, int M) {
    int gw = (blockIdx.x * blockDim.x + threadIdx.x) >> 5;
    int lane = threadIdx.x & 31;
    if (gw >= M) return;
    const float* row = y1 + (size_t)gw * Y1LD;
    float s = 0.f;
    for (int k = lane; k < DIM; k += 32) s += row[k] * w2[k];
    #pragma unroll
    for (int o = 16; o; o >>= 1) s += __shfl_xor_sync(0xffffffffu, s, o);
    if (lane == 0) {
        float v = s + b2[0];
        out[gw] = v > 0.f ? v : 0.2f * v;
    }
}

// ---------------- fp32 NT GEMM (GCN + gx) ----------------
__global__ void __launch_bounds__(256, 2) gemm_nt128(
    const float* __restrict__ A, const float* __restrict__ Bm,
    const float* __restrict__ bias, float* __restrict__ C,
    int M, int N, int K, int ldc, int act)
{
    __shared__ __align__(16) float As[8][128];
    __shared__ __align__(16) float Bs[8][128];
    int tid = threadIdx.x;
    int m0 = blockIdx.y * 128, n0 = blockIdx.x * 128;
    int ty = tid >> 4, tx = tid & 15;
    int ar = tid >> 1, ak = (tid & 1) * 4;
    int am = m0 + ar; if (am >= M) am = M - 1;
    int bn = n0 + ar; if (bn >= N) bn = N - 1;
    const float* Ap = A + (size_t)am * K + ak;
    const float* Bp = Bm + (size_t)bn * K + ak;
    ull acc[4][8];
    #pragma unroll
    for (int i = 0; i < 4; i++)
        #pragma unroll
        for (int j = 0; j < 8; j++) acc[i][j] = 0ull;
    float4 apf = *(const float4*)Ap;
    float4 bpf = *(const float4*)Bp;
    for (int k0 = 0; k0 < K; k0 += 8) {
        As[ak + 0][ar] = apf.x; As[ak + 1][ar] = apf.y;
        As[ak + 2][ar] = apf.z; As[ak + 3][ar] = apf.w;
        Bs[ak + 0][ar] = bpf.x; Bs[ak + 1][ar] = bpf.y;
        Bs[ak + 2][ar] = bpf.z; Bs[ak + 3][ar] = bpf.w;
        __syncthreads();
        if (k0 + 8 < K) {
            apf = *(const float4*)(Ap + k0 + 8);
            bpf = *(const float4*)(Bp + k0 + 8);
        }
        #pragma unroll
        for (int kk = 0; kk < 8; kk++) {
            ulonglong2 a01 = *(const ulonglong2*)&As[kk][ty * 8];
            ulonglong2 a23 = *(const ulonglong2*)&As[kk][ty * 8 + 4];
            float4 bv0 = *(const float4*)&Bs[kk][tx * 8];
            float4 bv1 = *(const float4*)&Bs[kk][tx * 8 + 4];
            ull bd[8];
            bd[0] = dup2(bv0.x); bd[1] = dup2(bv0.y); bd[2] = dup2(bv0.z); bd[3] = dup2(bv0.w);
            bd[4] = dup2(bv1.x); bd[5] = dup2(bv1.y); bd[6] = dup2(bv1.z); bd[7] = dup2(bv1.w);
            ull av[4] = {a01.x, a01.y, a23.x, a23.y};
            #pragma unroll
            for (int i = 0; i < 4; i++)
                #pragma unroll
                for (int j = 0; j < 8; j++) ffma2(acc[i][j], av[i], bd[j]);
        }
        __syncthreads();
    }
    #pragma unroll
    for (int i = 0; i < 4; i++) {
        int gm0 = m0 + ty * 8 + 2 * i;
        #pragma unroll
        for (int j = 0; j < 8; j++) {
            int gn = n0 + tx * 8 + j;
            if (gn >= N) continue;
            float b = bias ? bias[gn] : 0.f;
            float v0 = lo32(acc[i][j]) + b;
            float v1 = hi32(acc[i][j]) + b;
            if (act == 1) { v0 = fmaxf(v0, 0.f); v1 = fmaxf(v1, 0.f); }
            if (gm0 < M)     C[(size_t)gm0 * ldc + gn] = v0;
            if (gm0 + 1 < M) C[(size_t)(gm0 + 1) * ldc + gn] = v1;
        }
    }
}

// ---------------- wmma bf16 hi/lo NT GEMM (static smem + register prefetch) ----------------
#define SP 40
__global__ void __launch_bounds__(256) wmma_nt(
    const bf16* __restrict__ Ah, const bf16* __restrict__ Al,
    const bf16* __restrict__ Bh, const bf16* __restrict__ Bl,
    float* __restrict__ C,
    int M, int N, int K, int lda, int ldb, int Brows, int ldc,
    size_t sA, size_t sB, size_t sC, int accInit)
{
    Ah += sA * blockIdx.z; Al += sA * blockIdx.z;
    Bh += sB * blockIdx.z; Bl += sB * blockIdx.z;
    C  += sC * blockIdx.z;
    __shared__ __align__(32) bf16 As[2][128 * SP];
    __shared__ __align__(32) bf16 Bs[2][128 * SP];
    int tid = threadIdx.x, wid = tid >> 5;
    int m0 = blockIdx.y * 128, n0 = blockIdx.x * 128;
    int wm = wid >> 2, wn = wid & 3;

    wmma::fragment<wmma::accumulator, 16, 16, 16, float> acc[4][2];
    #pragma unroll
    for (int i = 0; i < 4; i++)
        #pragma unroll
        for (int j = 0; j < 2; j++) {
            int gm = m0 + wm * 64 + i * 16, gn = n0 + wn * 32 + j * 16;
            if (accInit && gm + 16 <= M && gn + 16 <= N)
                wmma::load_matrix_sync(acc[i][j], C + (size_t)gm * ldc + gn, ldc, wmma::mem_row_major);
            else
                wmma::fill_fragment(acc[i][j], 0.f);
        }

    int r = tid >> 1, col = (tid & 1) * 16;
    int ga = m0 + r; if (ga > M - 1) ga = M - 1;
    int gb = n0 + r; if (gb > Brows - 1) gb = Brows - 1;
    const bf16* pAh = Ah + (size_t)ga * lda + col;
    const bf16* pAl = Al + (size_t)ga * lda + col;
    const bf16* pBh = Bh + (size_t)gb * ldb + col;
    const bf16* pBl = Bl + (size_t)gb * ldb + col;
    unsigned dof = (unsigned)(r * SP + col);

    // prefetch k0 = 0
    uint4 vah0 = *(const uint4*)(pAh),     vah1 = *(const uint4*)(pAh + 8);
    uint4 val0 = *(const uint4*)(pAl),     val1 = *(const uint4*)(pAl + 8);
    uint4 vbh0 = *(const uint4*)(pBh),     vbh1 = *(const uint4*)(pBh + 8);
    uint4 vbl0 = *(const uint4*)(pBl),     vbl1 = *(const uint4*)(pBl + 8);

    for (int k0 = 0; k0 < K; k0 += 32) {
        *(uint4*)&As[0][dof]     = vah0;  *(uint4*)&As[0][dof + 8] = vah1;
        *(uint4*)&As[1][dof]     = val0;  *(uint4*)&As[1][dof + 8] = val1;
        *(uint4*)&Bs[0][dof]     = vbh0;  *(uint4*)&Bs[0][dof + 8] = vbh1;
        *(uint4*)&Bs[1][dof]     = vbl0;  *(uint4*)&Bs[1][dof + 8] = vbl1;
        __syncthreads();
        if (k0 + 32 < K) {
            int kn = k0 + 32;
            vah0 = *(const uint4*)(pAh + kn);  vah1 = *(const uint4*)(pAh + kn + 8);
            val0 = *(const uint4*)(pAl + kn);  val1 = *(const uint4*)(pAl + kn + 8);
            vbh0 = *(const uint4*)(pBh + kn);  vbh1 = *(const uint4*)(pBh + kn + 8);
            vbl0 = *(const uint4*)(pBl + kn);  vbl1 = *(const uint4*)(pBl + kn + 8);
        }
        #pragma unroll
        for (int ks = 0; ks < 32; ks += 16) {
            wmma::fragment<wmma::matrix_b, 16, 16, 16, bf16, wmma::col_major> bh[2], bl[2];
            #pragma unroll
            for (int j = 0; j < 2; j++) {
                wmma::load_matrix_sync(bh[j], &Bs[0][(wn * 32 + j * 16) * SP + ks], SP);
                wmma::load_matrix_sync(bl[j], &Bs[1][(wn * 32 + j * 16) * SP + ks], SP);
            }
            #pragma unroll
            for (int i = 0; i < 4; i++) {
                wmma::fragment<wmma::matrix_a, 16, 16, 16, bf16, wmma::row_major> ah, al;
                wmma::load_matrix_sync(ah, &As[0][(wm * 64 + i * 16) * SP + ks], SP);
                wmma::load_matrix_sync(al, &As[1][(wm * 64 + i * 16) * SP + ks], SP);
                #pragma unroll
                for (int j = 0; j < 2; j++) {
                    wmma::mma_sync(acc[i][j], ah, bh[j], acc[i][j]);
                    wmma::mma_sync(acc[i][j], ah, bl[j], acc[i][j]);
                    wmma::mma_sync(acc[i][j], al, bh[j], acc[i][j]);
                }
            }
        }
        __syncthreads();
    }
    #pragma unroll
    for (int i = 0; i < 4; i++)
        #pragma unroll
        for (int j = 0; j < 2; j++) {
            int gm = m0 + wm * 64 + i * 16, gn = n0 + wn * 32 + j * 16;
            if (gm + 16 <= M && gn + 16 <= N)
                wmma::store_matrix_sync(C + (size_t)gm * ldc + gn, acc[i][j], ldc, wmma::mem_row_major);
        }
}

// ---------------- GRU scan ----------------
__global__ void __launch_bounds__(640) gru_scan(
    const float* __restrict__ gxbase,
    const float* __restrict__ whht_f, const float* __restrict__ whht_b,
    const float* __restrict__ bhh_f,  const float* __restrict__ bhh_b,
    const int* __restrict__ lenT, const int* __restrict__ lenA,
    float* __restrict__ xoutT, float* __restrict__ xoutA)
{
    int b = blockIdx.x, d = blockIdx.y, br = blockIdx.z;
    int T = br ? T_AB : T_TI;
    int len = (br ? lenA : lenT)[b];
    if (len < 0) len = 0;
    if (len > T) len = T;
    const float* gx = gxbase + (size_t)(br * 2 + d) * GXS + (size_t)b * T * G3;
    float* xout = (br ? xoutA : xoutT) + (size_t)b * T * (2 * DIM) + d * DIM;
    const float* whht = d ? whht_b : whht_f;
    const float* bhh  = d ? bhh_b  : bhh_f;
    __shared__ __align__(16) float h_s[DIM];
    __shared__ float gh_s[G3];
    int tid = threadIdx.x;
    if (tid < DIM) h_s[tid] = 0.f;
    float bh = (tid < G3) ? bhh[tid] : 0.f;
    const float* wcol = whht + tid * 2;
    __syncthreads();
    for (int s = 0; s < len; s++) {
        int t = d ? (len - 1 - s) : s;
        if (tid < G3) {
            const ull* h2 = (const ull*)h_s;
            ull a0 = 0ull, a1 = 0ull, a2 = 0ull, a3 = 0ull;
            #pragma unroll 5
            for (int p = 0; p < DIM / 2; p += 4) {
                ffma2(a0, h2[p + 0], *(const ull*)(wcol + (size_t)(p + 0) * (2 * G3)));
                ffma2(a1, h2[p + 1], *(const ull*)(wcol + (size_t)(p + 1) * (2 * G3)));
                ffma2(a2, h2[p + 2], *(const ull*)(wcol + (size_t)(p + 2) * (2 * G3)));
                ffma2(a3, h2[p + 3], *(const ull*)(wcol + (size_t)(p + 3) * (2 * G3)));
            }
            gh_s[tid] = bh + lo32(a0) + hi32(a0) + lo32(a1) + hi32(a1)
                           + lo32(a2) + hi32(a2) + lo32(a3) + hi32(a3);
        }
        __syncthreads();
        if (tid < DIM) {
            const float* g = gx + (size_t)t * G3;
            float r = 1.f / (1.f + expf(-(g[tid]           + gh_s[tid])));
            float z = 1.f / (1.f + expf(-(g[DIM + tid]     + gh_s[DIM + tid])));
            float n = tanhf(g[2 * DIM + tid] + r * gh_s[2 * DIM + tid]);
            float hn = (1.f - z) * n + z * h_s[tid];
            h_s[tid] = hn;
            xout[(size_t)t * (2 * DIM) + tid] = hn;
        }
        __syncthreads();
    }
}

// ---------------- launcher ----------------
static inline int ceildiv(int a, int b) { return (a + b - 1) / b; }

extern "C" void kernel_launch(void* const* d_in, const int* in_sizes, int n_in,
                              void* d_out, int out_size) {
    (void)in_sizes; (void)n_in; (void)out_size;
    const int*   in_ab   = (const int*)d_in[0];
    const int*   in_ti   = (const int*)d_in[1];
    const int*   ab_len  = (const int*)d_in[2];
    const int*   ti_len  = (const int*)d_in[3];
    const int*   esrc    = (const int*)d_in[4];
    const int*   edst    = (const int*)d_in[5];
    const float* gnf     = (const float*)d_in[6];
    const float* emb     = (const float*)d_in[7];
    const float* wih_l0f = (const float*)d_in[8];
    const float* whh_l0f = (const float*)d_in[9];
    const float* bih_l0f = (const float*)d_in[10];
    const float* bhh_l0f = (const float*)d_in[11];
    const float* wih_l0b = (const float*)d_in[12];
    const float* whh_l0b = (const float*)d_in[13];
    const float* bih_l0b = (const float*)d_in[14];
    const float* bhh_l0b = (const float*)d_in[15];
    const float* wih_l1f = (const float*)d_in[16];
    const float* whh_l1f = (const float*)d_in[17];
    const float* bih_l1f = (const float*)d_in[18];
    const float* bhh_l1f = (const float*)d_in[19];
    const float* wih_l1b = (const float*)d_in[20];
    const float* whh_l1b = (const float*)d_in[21];
    const float* bih_l1b = (const float*)d_in[22];
    const float* bhh_l1b = (const float*)d_in[23];
    const float* gcn_w1  = (const float*)d_in[24];
    const float* gcn_b1  = (const float*)d_in[25];
    const float* gcn_w2  = (const float*)d_in[26];
    const float* gcn_b2  = (const float*)d_in[27];
    const float* fc1_w   = (const float*)d_in[28];
    const float* fc1_b   = (const float*)d_in[29];
    const float* fc2_w   = (const float*)d_in[30];
    const float* fc2_b   = (const float*)d_in[31];
    float* out = (float*)d_out;

    float* S = nullptr;  cudaGetSymbolAddress((void**)&S, SCR);
    bf16* Bb = nullptr;  cudaGetSymbolAddress((void**)&Bb, BSCR);
    float* AGG  = S + OFF_AGG;
    float* HB   = S + OFF_HB;
    float* LF   = S + OFF_LF;
    float* X0T  = S + OFF_X0T;
    float* X0A  = S + OFF_X0A;
    float* XL0T = S + OFF_XL0T;
    float* XL0A = S + OFF_XL0A;
    float* XL1T = S + OFF_XL1T;
    float* XL1A = S + OFF_XL1A;
    float* GX   = S + OFF_GX;
    float* WHHT = S + OFF_WHHT;
    float* LOG  = S + OFF_LOG;
    float* FEAT = S + OFF_FEAT;
    float* Y1   = S + OFF_Y1;

    cudaMemsetAsync(AGG,  0, SZ_AGG  * 4);
    cudaMemsetAsync(XL0T, 0, SZ_XL0T * 4);
    cudaMemsetAsync(XL0A, 0, SZ_XL0A * 4);
    cudaMemsetAsync(XL1T, 0, SZ_XL0T * 4);
    cudaMemsetAsync(XL1A, 0, SZ_XL0A * 4);

    {
        int blks = ceildiv(G3 * DIM, 256);
        pack_whh<<<blks, 256>>>(whh_l0f, WHHT + 0 * (size_t)DIM * G3);
        pack_whh<<<blks, 256>>>(whh_l0b, WHHT + 1 * (size_t)DIM * G3);
        pack_whh<<<blks, 256>>>(whh_l1f, WHHT + 2 * (size_t)DIM * G3);
        pack_whh<<<blks, 256>>>(whh_l1b, WHHT + 3 * (size_t)DIM * G3);
    }
    gather_emb<<<ceildiv(BATCH * T_TI * DIM, 256), 256>>>(in_ti, emb, X0T, BATCH * T_TI * DIM);
    gather_emb<<<ceildiv(BATCH * T_AB * DIM, 256), 256>>>(in_ab, emb, X0A, BATCH * T_AB * DIM);
    f2b2_pad<<<ceildiv(200 * KP, 256), 256>>>(fc1_w, Bb + B_FWH, Bb + B_FWL, 200, 400, KP);

    // ---- GCN ----
    {
        long total = (long)NEDGES * (DIM / 4);
        int blks = (int)((total + 255) / 256);
        gcn_agg<<<blks, 256>>>(gnf, esrc, edst, AGG);
        dim3 g1(ceildiv(DIM, 128), ceildiv(NL, 128), 1);
        gemm_nt128<<<g1, 256>>>(AGG, gcn_w1, gcn_b1, HB, NL, DIM, DIM, DIM, 1);
        cudaMemsetAsync(AGG, 0, SZ_AGG * 4);
        gcn_agg<<<blks, 256>>>(HB, esrc, edst, AGG);
        gemm_nt128<<<g1, 256>>>(AGG, gcn_w2, gcn_b2, LF, NL, DIM, DIM, 2 * DIM, 0);
        copy_to_lf<<<ceildiv(NL * DIM, 256), 256>>>(gnf, LF);
        f2b2_pad<<<(int)(((long)NL * KP + 255) / 256), 256>>>(LF, Bb + B_LFH, Bb + B_LFL, NL, 400, KP);
    }

    // ---- GRU layer 0 ----
    {
        dim3 gT(ceildiv(G3, 128), ceildiv(BATCH * T_TI, 128), 1);
        dim3 gA(ceildiv(G3, 128), ceildiv(BATCH * T_AB, 128), 1);
        gemm_nt128<<<gT, 256>>>(X0T, wih_l0f, bih_l0f, GX + 0 * GXS, BATCH * T_TI, G3, DIM, G3, 0);
        gemm_nt128<<<gT, 256>>>(X0T, wih_l0b, bih_l0b, GX + 1 * GXS, BATCH * T_TI, G3, DIM, G3, 0);
        gemm_nt128<<<gA, 256>>>(X0A, wih_l0f, bih_l0f, GX + 2 * GXS, BATCH * T_AB, G3, DIM, G3, 0);
        gemm_nt128<<<gA, 256>>>(X0A, wih_l0b, bih_l0b, GX + 3 * GXS, BATCH * T_AB, G3, DIM, G3, 0);
        dim3 gs(BATCH, 2, 2);
        gru_scan<<<gs, 640>>>(GX, WHHT + 0 * (size_t)DIM * G3, WHHT + 1 * (size_t)DIM * G3,
                              bhh_l0f, bhh_l0b, ti_len, ab_len, XL0T, XL0A);
    }
    // ---- GRU layer 1 ----
    {
        dim3 gT(ceildiv(G3, 128), ceildiv(BATCH * T_TI, 128), 1);
        dim3 gA(ceildiv(G3, 128), ceildiv(BATCH * T_AB, 128), 1);
        gemm_nt128<<<gT, 256>>>(XL0T, wih_l1f, bih_l1f, GX + 0 * GXS, BATCH * T_TI, G3, 2 * DIM, G3, 0);
        gemm_nt128<<<gT, 256>>>(XL0T, wih_l1b, bih_l1b, GX + 1 * GXS, BATCH * T_TI, G3, 2 * DIM, G3, 0);
        gemm_nt128<<<gA, 256>>>(XL0A, wih_l1f, bih_l1f, GX + 2 * GXS, BATCH * T_AB, G3, 2 * DIM, G3, 0);
        gemm_nt128<<<gA, 256>>>(XL0A, wih_l1b, bih_l1b, GX + 3 * GXS, BATCH * T_AB, G3, 2 * DIM, G3, 0);
        dim3 gs(BATCH, 2, 2);
        gru_scan<<<gs, 640>>>(GX, WHHT + 2 * (size_t)DIM * G3, WHHT + 3 * (size_t)DIM * G3,
                              bhh_l1f, bhh_l1b, ti_len, ab_len, XL1T, XL1A);
    }

    // ---- bf16 conversions of GRU outputs ----
    f2b2_pad<<<ceildiv(BATCH * T_TI * KP, 256), 256>>>(XL1T, Bb + B_XTIH, Bb + B_XTIL,
                                                        BATCH * T_TI, 400, KP);
    f2b2_pad<<<ceildiv(BATCH * T_AB * KP, 256), 256>>>(XL1A, Bb + B_XAIH, Bb + B_XAIL,
                                                        BATCH * T_AB, 400, KP);
    build_xt<<<ceildiv(BATCH * 400 * T_TI, 256), 256>>>(XL1T, Bb + B_XTTH, Bb + B_XTTL, T_TI);
    build_xt<<<ceildiv(BATCH * 400 * T_AB, 256), 256>>>(XL1A, Bb + B_XTAH, Bb + B_XTAL, T_AB);

    int gy = ceildiv(NL, 128);
    // ---- title attention ----
    {
        dim3 gl(1, gy, BATCH);
        wmma_nt<<<gl, 256>>>(Bb + B_LFH, Bb + B_LFL, Bb + B_XTIH, Bb + B_XTIL, LOG,
                             NL, T_TI, KP, KP, KP, T_TI, T_TI,
                             0, (size_t)T_TI * KP, (size_t)NL * T_TI, 0);
        softmax_pb<<<ceildiv(BATCH * NL, 8), 256>>>(LOG, Bb + B_PH, Bb + B_PL, BATCH * NL, T_TI);
        dim3 gw(ceildiv(400, 128), gy, BATCH);
        wmma_nt<<<gw, 256>>>(Bb + B_PH, Bb + B_PL, Bb + B_XTTH, Bb + B_XTTL, FEAT,
                             NL, 400, T_TI, T_TI, T_TI, 400, 400,
                             (size_t)NL * T_TI, (size_t)400 * T_TI, (size_t)NL * 400, 0);
    }
    // ---- abstract attention (accumulates into FEAT) ----
    {
        dim3 gl(ceildiv(T_AB, 128), gy, BATCH);
        wmma_nt<<<gl, 256>>>(Bb + B_LFH, Bb + B_LFL, Bb + B_XAIH, Bb + B_XAIL, LOG,
                             NL, T_AB, KP, KP, KP, T_AB, T_AB,
                             0, (size_t)T_AB * KP, (size_t)NL * T_AB, 0);
        softmax_pb<<<ceildiv(BATCH * NL, 8), 256>>>(LOG, Bb + B_PH, Bb + B_PL, BATCH * NL, T_AB);
        dim3 gw(ceildiv(400, 128), gy, BATCH);
        wmma_nt<<<gw, 256>>>(Bb + B_PH, Bb + B_PL, Bb + B_XTAH, Bb + B_XTAL, FEAT,
                             NL, 400, T_AB, T_AB, T_AB, 400, 400,
                             (size_t)NL * T_AB, (size_t)400 * T_AB, (size_t)NL * 400, 1);
    }

    // ---- output head ----
    {
        f2b2_pad<<<(int)(((long)BATCH * NL * KP + 255) / 256), 256>>>(
            FEAT, Bb + B_FH, Bb + B_FL, (long)BATCH * NL, 400, KP);
        dim3 gf(2, ceildiv(BATCH * NL, 128), 1);
        wmma_nt<<<gf, 256>>>(Bb + B_FH, Bb + B_FL, Bb + B_FWH, Bb + B_FWL, Y1,
                             BATCH * NL, Y1LD, KP, KP, KP, 200, Y1LD,
                             0, 0, 0, 0);
        bias_leaky<<<(int)(((long)BATCH * NL * 200 + 255) / 256), 256>>>(Y1, fc1_b, (long)BATCH * NL);
        fc2_kernel<<<ceildiv(BATCH * NL, 8), 256>>>(Y1, fc2_w, fc2_b, out, BATCH * NL);
    }
}

// round 11
// speedup vs baseline: 1.1057x; 1.0446x over previous
#include <cuda_runtime.h>
#include <cuda_bf16.h>
#include <mma.h>
#include <math.h>
#include <stdint.h>

using namespace nvcuda;
typedef unsigned long long ull;
typedef __nv_bfloat16 bf16;

#define NL      28000
#define DIM     200
#define NEDGES  224000
#define BATCH   4
#define T_TI    64
#define T_AB    384
#define G3      600
#define KP      448
#define KC      448   /* fused ws K = T_TI + T_AB */
#define Y1LD    208

// ---------------- f32x2 helpers ----------------
__device__ __forceinline__ ull dup2(float x) {
    ull r; unsigned u = __float_as_uint(x);
    asm("mov.b64 %0, {%1, %1};" : "=l"(r) : "r"(u));
    return r;
}
__device__ __forceinline__ void ffma2(ull& d, ull a, ull b) {
    asm("fma.rn.f32x2 %0, %1, %2, %0;" : "+l"(d) : "l"(a), "l"(b));
}
__device__ __forceinline__ float lo32(ull v) { return __uint_as_float((unsigned)v); }
__device__ __forceinline__ float hi32(ull v) { return __uint_as_float((unsigned)(v >> 32)); }

// ---------------- fp32 scratch ----------------
__host__ __device__ constexpr size_t rnd1k(size_t x) { return (x + 1023) & ~(size_t)1023; }
constexpr size_t SZ_AGG  = (size_t)NL * DIM;
constexpr size_t SZ_LF   = (size_t)NL * 2 * DIM;
constexpr size_t SZ_X0T  = (size_t)BATCH * T_TI * DIM;
constexpr size_t SZ_X0A  = (size_t)BATCH * T_AB * DIM;
constexpr size_t SZ_XL0T = (size_t)BATCH * T_TI * 2 * DIM;
constexpr size_t SZ_XL0A = (size_t)BATCH * T_AB * 2 * DIM;
constexpr size_t GXS     = (size_t)BATCH * T_AB * G3;
constexpr size_t OFF_AGG  = 0;
constexpr size_t OFF_HB   = OFF_AGG  + rnd1k(SZ_AGG);
constexpr size_t OFF_LF   = OFF_HB   + rnd1k(SZ_AGG);
constexpr size_t OFF_X0T  = OFF_LF   + rnd1k(SZ_LF);
constexpr size_t OFF_X0A  = OFF_X0T  + rnd1k(SZ_X0T);
constexpr size_t OFF_XL0T = OFF_X0A  + rnd1k(SZ_X0A);
constexpr size_t OFF_XL0A = OFF_XL0T + rnd1k(SZ_XL0T);
constexpr size_t OFF_XL1T = OFF_XL0A + rnd1k(SZ_XL0A);
constexpr size_t OFF_XL1A = OFF_XL1T + rnd1k(SZ_XL0T);
constexpr size_t OFF_GX   = OFF_XL1A + rnd1k(SZ_XL0A);
constexpr size_t OFF_WHHT = OFF_GX   + rnd1k(4 * GXS);
constexpr size_t OFF_LOG  = OFF_WHHT + rnd1k(4 * (size_t)DIM * G3);
constexpr size_t OFF_FEAT = OFF_LOG  + rnd1k((size_t)BATCH * NL * T_AB);
constexpr size_t OFF_Y1   = OFF_FEAT + rnd1k((size_t)BATCH * NL * 2 * DIM);
constexpr size_t SCR_TOTAL = OFF_Y1  + rnd1k((size_t)BATCH * NL * Y1LD);
__device__ float SCR[SCR_TOTAL];

// ---------------- bf16 hi/lo scratch ----------------
constexpr size_t NLF  = (size_t)NL * KP;
constexpr size_t NXTI = (size_t)BATCH * T_TI * KP;
constexpr size_t NXAI = (size_t)BATCH * T_AB * KP;
constexpr size_t NXC  = (size_t)BATCH * 400 * KC;     // fused transposed X
constexpr size_t NP2  = (size_t)BATCH * NL * KC;      // fused probs
constexpr size_t NF   = (size_t)BATCH * NL * KP;
constexpr size_t NFW  = (size_t)200 * KP;
constexpr size_t B_LFH  = 0;
constexpr size_t B_LFL  = B_LFH  + NLF;
constexpr size_t B_XTIH = B_LFL  + NLF;
constexpr size_t B_XTIL = B_XTIH + NXTI;
constexpr size_t B_XAIH = B_XTIL + NXTI;
constexpr size_t B_XAIL = B_XAIH + NXAI;
constexpr size_t B_XCH  = B_XAIL + NXAI;
constexpr size_t B_XCL  = B_XCH  + NXC;
constexpr size_t B_PH   = B_XCL  + NXC;
constexpr size_t B_PL   = B_PH   + NP2;
constexpr size_t B_FH   = B_PL   + NP2;
constexpr size_t B_FL   = B_FH   + NF;
constexpr size_t B_FWH  = B_FL   + NF;
constexpr size_t B_FWL  = B_FWH  + NFW;
constexpr size_t BTOT   = B_FWL  + NFW;
__device__ __align__(128) bf16 BSCR[BTOT];

// ---------------- helper kernels ----------------
__global__ void gather_emb(const int* __restrict__ tok, const float* __restrict__ emb,
                           float* __restrict__ x, int total) {
    int idx = blockIdx.x * blockDim.x + threadIdx.x;
    if (idx >= total) return;
    int i = idx / DIM, f = idx - i * DIM;
    x[idx] = emb[(size_t)tok[i] * DIM + f];
}
__global__ void pack_whh(const float* __restrict__ w, float* __restrict__ wt) {
    int idx = blockIdx.x * blockDim.x + threadIdx.x;
    if (idx >= G3 * DIM) return;
    int g = idx / DIM, k = idx - g * DIM;
    wt[(size_t)(k >> 1) * (G3 * 2) + g * 2 + (k & 1)] = w[idx];
}
__global__ void copy_to_lf(const float* __restrict__ gnf, float* __restrict__ lf) {
    int idx = blockIdx.x * blockDim.x + threadIdx.x;
    if (idx >= NL * DIM) return;
    int n = idx / DIM, k = idx - n * DIM;
    lf[(size_t)n * (2 * DIM) + DIM + k] = gnf[idx];
}
__global__ void gcn_agg(const float* __restrict__ feat, const int* __restrict__ src,
                        const int* __restrict__ dst, float* __restrict__ agg) {
    long idx = (long)blockIdx.x * blockDim.x + threadIdx.x;
    const long total = (long)NEDGES * (DIM / 4);
    if (idx >= total) return;
    int e = (int)(idx / (DIM / 4));
    int q = (int)(idx - (long)e * (DIM / 4));
    const float4 v = ((const float4*)(feat + (size_t)src[e] * DIM))[q];
    float* a = agg + (size_t)dst[e] * DIM + q * 4;
    atomicAdd(a + 0, v.x); atomicAdd(a + 1, v.y);
    atomicAdd(a + 2, v.z); atomicAdd(a + 3, v.w);
}
__global__ void f2b2_pad(const float* __restrict__ in, bf16* __restrict__ oh,
                         bf16* __restrict__ ol, long rows, int cin, int cout) {
    long idx = (long)blockIdx.x * blockDim.x + threadIdx.x;
    if (idx >= rows * cout) return;
    long r = idx / cout; int c = (int)(idx - r * cout);
    float x = (c < cin) ? in[r * cin + c] : 0.f;
    bf16 h = __float2bfloat16(x);
    oh[idx] = h;
    ol[idx] = __float2bfloat16(x - __bfloat162float(h));
}
// X[b,t,400] -> XC[b,d,off+t] (ld KC), hi/lo
__global__ void build_xtc(const float* __restrict__ x, bf16* __restrict__ oh,
                          bf16* __restrict__ ol, int T, int off) {
    long idx = (long)blockIdx.x * blockDim.x + threadIdx.x;
    long total = (long)BATCH * 400 * T;
    if (idx >= total) return;
    int t = (int)(idx % T);
    int d = (int)((idx / T) % 400);
    int b = (int)(idx / ((long)400 * T));
    float v = x[((long)b * T + t) * 400 + d];
    bf16 h = __float2bfloat16(v);
    size_t o = ((size_t)b * 400 + d) * KC + off + t;
    oh[o] = h;
    ol[o] = __float2bfloat16(v - __bfloat162float(h));
}
// softmax rows of LOG [rows x T] -> probs into P[row][off..off+T) (ld KC)
__global__ void softmax_pb(const float* __restrict__ logits, bf16* __restrict__ ph,
                           bf16* __restrict__ pl, int rows, int T, int off) {
    int gw = (blockIdx.x * blockDim.x + threadIdx.x) >> 5;
    int lane = threadIdx.x & 31;
    if (gw >= rows) return;
    const float* p = logits + (size_t)gw * T;
    float v[12];
    int cnt = 0;
    float mx = -1e30f;
    for (int i = lane; i < T; i += 32) { float x = p[i]; v[cnt++] = x; mx = fmaxf(mx, x); }
    #pragma unroll
    for (int o = 16; o; o >>= 1) mx = fmaxf(mx, __shfl_xor_sync(0xffffffffu, mx, o));
    float s = 0.f;
    for (int c = 0; c < cnt; c++) { v[c] = expf(v[c] - mx); s += v[c]; }
    #pragma unroll
    for (int o = 16; o; o >>= 1) s += __shfl_xor_sync(0xffffffffu, s, o);
    float inv = 1.f / s;
    cnt = 0;
    size_t base = (size_t)gw * KC + off;
    for (int i = lane; i < T; i += 32) {
        float pv = v[cnt++] * inv;
        bf16 h = __float2bfloat16(pv);
        ph[base + i] = h;
        pl[base + i] = __float2bfloat16(pv - __bfloat162float(h));
    }
}
__global__ void bias_leaky(float* __restrict__ y, const float* __restrict__ b, long rows) {
    long idx = (long)blockIdx.x * blockDim.x + threadIdx.x;
    if (idx >= rows * 200) return;
    long r = idx / 200; int c = (int)(idx - r * 200);
    float v = y[r * Y1LD + c] + b[c];
    y[r * Y1LD + c] = v > 0.f ? v : 0.2f * v;
}
__global__ void fc2_kernel(const float* __restrict__ y1, const float* __restrict__ w2,
                           const float* __restrict__ b2, float* __restrict__ out, int M) {
    int gw = (blockIdx.x * blockDim.x + threadIdx.x) >> 5;
    int lane = threadIdx.x & 31;
    if (gw >= M) return;
    const float* row = y1 + (size_t)gw * Y1LD;
    float s = 0.f;
    for (int k = lane; k < DIM; k += 32) s += row[k] * w2[k];
    #pragma unroll
    for (int o = 16; o; o >>= 1) s += __shfl_xor_sync(0xffffffffu, s, o);
    if (lane == 0) {
        float v = s + b2[0];
        out[gw] = v > 0.f ? v : 0.2f * v;
    }
}

// ---------------- fp32 NT GEMM (GCN + gx) ----------------
__global__ void __launch_bounds__(256, 2) gemm_nt128(
    const float* __restrict__ A, const float* __restrict__ Bm,
    const float* __restrict__ bias, float* __restrict__ C,
    int M, int N, int K, int ldc, int act)
{
    __shared__ __align__(16) float As[8][128];
    __shared__ __align__(16) float Bs[8][128];
    int tid = threadIdx.x;
    int m0 = blockIdx.y * 128, n0 = blockIdx.x * 128;
    int ty = tid >> 4, tx = tid & 15;
    int ar = tid >> 1, ak = (tid & 1) * 4;
    int am = m0 + ar; if (am >= M) am = M - 1;
    int bn = n0 + ar; if (bn >= N) bn = N - 1;
    const float* Ap = A + (size_t)am * K + ak;
    const float* Bp = Bm + (size_t)bn * K + ak;
    ull acc[4][8];
    #pragma unroll
    for (int i = 0; i < 4; i++)
        #pragma unroll
        for (int j = 0; j < 8; j++) acc[i][j] = 0ull;
    float4 apf = *(const float4*)Ap;
    float4 bpf = *(const float4*)Bp;
    for (int k0 = 0; k0 < K; k0 += 8) {
        As[ak + 0][ar] = apf.x; As[ak + 1][ar] = apf.y;
        As[ak + 2][ar] = apf.z; As[ak + 3][ar] = apf.w;
        Bs[ak + 0][ar] = bpf.x; Bs[ak + 1][ar] = bpf.y;
        Bs[ak + 2][ar] = bpf.z; Bs[ak + 3][ar] = bpf.w;
        __syncthreads();
        if (k0 + 8 < K) {
            apf = *(const float4*)(Ap + k0 + 8);
            bpf = *(const float4*)(Bp + k0 + 8);
        }
        #pragma unroll
        for (int kk = 0; kk < 8; kk++) {
            ulonglong2 a01 = *(const ulonglong2*)&As[kk][ty * 8];
            ulonglong2 a23 = *(const ulonglong2*)&As[kk][ty * 8 + 4];
            float4 bv0 = *(const float4*)&Bs[kk][tx * 8];
            float4 bv1 = *(const float4*)&Bs[kk][tx * 8 + 4];
            ull bd[8];
            bd[0] = dup2(bv0.x); bd[1] = dup2(bv0.y); bd[2] = dup2(bv0.z); bd[3] = dup2(bv0.w);
            bd[4] = dup2(bv1.x); bd[5] = dup2(bv1.y); bd[6] = dup2(bv1.z); bd[7] = dup2(bv1.w);
            ull av[4] = {a01.x, a01.y, a23.x, a23.y};
            #pragma unroll
            for (int i = 0; i < 4; i++)
                #pragma unroll
                for (int j = 0; j < 8; j++) ffma2(acc[i][j], av[i], bd[j]);
        }
        __syncthreads();
    }
    #pragma unroll
    for (int i = 0; i < 4; i++) {
        int gm0 = m0 + ty * 8 + 2 * i;
        #pragma unroll
        for (int j = 0; j < 8; j++) {
            int gn = n0 + tx * 8 + j;
            if (gn >= N) continue;
            float b = bias ? bias[gn] : 0.f;
            float v0 = lo32(acc[i][j]) + b;
            float v1 = hi32(acc[i][j]) + b;
            if (act == 1) { v0 = fmaxf(v0, 0.f); v1 = fmaxf(v1, 0.f); }
            if (gm0 < M)     C[(size_t)gm0 * ldc + gn] = v0;
            if (gm0 + 1 < M) C[(size_t)(gm0 + 1) * ldc + gn] = v1;
        }
    }
}

// ---------------- wmma bf16 hi/lo NT GEMM (R8-exact) ----------------
#define SP 40
__global__ void __launch_bounds__(256) wmma_nt(
    const bf16* __restrict__ Ah, const bf16* __restrict__ Al,
    const bf16* __restrict__ Bh, const bf16* __restrict__ Bl,
    float* __restrict__ C,
    int M, int N, int K, int lda, int ldb, int Brows, int ldc,
    size_t sA, size_t sB, size_t sC, int accInit)
{
    Ah += sA * blockIdx.z; Al += sA * blockIdx.z;
    Bh += sB * blockIdx.z; Bl += sB * blockIdx.z;
    C  += sC * blockIdx.z;
    __shared__ __align__(32) bf16 As[2][128 * SP];
    __shared__ __align__(32) bf16 Bs[2][128 * SP];
    int tid = threadIdx.x, wid = tid >> 5;
    int m0 = blockIdx.y * 128, n0 = blockIdx.x * 128;
    int wm = wid >> 2, wn = wid & 3;

    wmma::fragment<wmma::accumulator, 16, 16, 16, float> acc[4][2];
    #pragma unroll
    for (int i = 0; i < 4; i++)
        #pragma unroll
        for (int j = 0; j < 2; j++) {
            int gm = m0 + wm * 64 + i * 16, gn = n0 + wn * 32 + j * 16;
            if (accInit && gm + 16 <= M && gn + 16 <= N)
                wmma::load_matrix_sync(acc[i][j], C + (size_t)gm * ldc + gn, ldc, wmma::mem_row_major);
            else
                wmma::fill_fragment(acc[i][j], 0.f);
        }

    int r = tid >> 1, col = (tid & 1) * 16;
    int ga = m0 + r; if (ga > M - 1) ga = M - 1;
    int gb = n0 + r; if (gb > Brows - 1) gb = Brows - 1;
    const bf16* pAh = Ah + (size_t)ga * lda + col;
    const bf16* pAl = Al + (size_t)ga * lda + col;
    const bf16* pBh = Bh + (size_t)gb * ldb + col;
    const bf16* pBl = Bl + (size_t)gb * ldb + col;
    unsigned dof = (unsigned)(r * SP + col);

    for (int k0 = 0; k0 < K; k0 += 32) {
        *(uint4*)&As[0][dof]     = *(const uint4*)(pAh + k0);
        *(uint4*)&As[0][dof + 8] = *(const uint4*)(pAh + k0 + 8);
        *(uint4*)&As[1][dof]     = *(const uint4*)(pAl + k0);
        *(uint4*)&As[1][dof + 8] = *(const uint4*)(pAl + k0 + 8);
        *(uint4*)&Bs[0][dof]     = *(const uint4*)(pBh + k0);
        *(uint4*)&Bs[0][dof + 8] = *(const uint4*)(pBh + k0 + 8);
        *(uint4*)&Bs[1][dof]     = *(const uint4*)(pBl + k0);
        *(uint4*)&Bs[1][dof + 8] = *(const uint4*)(pBl + k0 + 8);
        __syncthreads();
        #pragma unroll
        for (int ks = 0; ks < 32; ks += 16) {
            wmma::fragment<wmma::matrix_b, 16, 16, 16, bf16, wmma::col_major> bh[2], bl[2];
            #pragma unroll
            for (int j = 0; j < 2; j++) {
                wmma::load_matrix_sync(bh[j], &Bs[0][(wn * 32 + j * 16) * SP + ks], SP);
                wmma::load_matrix_sync(bl[j], &Bs[1][(wn * 32 + j * 16) * SP + ks], SP);
            }
            #pragma unroll
            for (int i = 0; i < 4; i++) {
                wmma::fragment<wmma::matrix_a, 16, 16, 16, bf16, wmma::row_major> ah, al;
                wmma::load_matrix_sync(ah, &As[0][(wm * 64 + i * 16) * SP + ks], SP);
                wmma::load_matrix_sync(al, &As[1][(wm * 64 + i * 16) * SP + ks], SP);
                #pragma unroll
                for (int j = 0; j < 2; j++) {
                    wmma::mma_sync(acc[i][j], ah, bh[j], acc[i][j]);
                    wmma::mma_sync(acc[i][j], ah, bl[j], acc[i][j]);
                    wmma::mma_sync(acc[i][j], al, bh[j], acc[i][j]);
                }
            }
        }
        __syncthreads();
    }
    #pragma unroll
    for (int i = 0; i < 4; i++)
        #pragma unroll
        for (int j = 0; j < 2; j++) {
            int gm = m0 + wm * 64 + i * 16, gn = n0 + wn * 32 + j * 16;
            if (gm + 16 <= M && gn + 16 <= N)
                wmma::store_matrix_sync(C + (size_t)gm * ldc + gn, acc[i][j], ldc, wmma::mem_row_major);
        }
}

// ---------------- GRU scan ----------------
__global__ void __launch_bounds__(640) gru_scan(
    const float* __restrict__ gxbase,
    const float* __restrict__ whht_f, const float* __restrict__ whht_b,
    const float* __restrict__ bhh_f,  const float* __restrict__ bhh_b,
    const int* __restrict__ lenT, const int* __restrict__ lenA,
    float* __restrict__ xoutT, float* __restrict__ xoutA)
{
    int b = blockIdx.x, d = blockIdx.y, br = blockIdx.z;
    int T = br ? T_AB : T_TI;
    int len = (br ? lenA : lenT)[b];
    if (len < 0) len = 0;
    if (len > T) len = T;
    const float* gx = gxbase + (size_t)(br * 2 + d) * GXS + (size_t)b * T * G3;
    float* xout = (br ? xoutA : xoutT) + (size_t)b * T * (2 * DIM) + d * DIM;
    const float* whht = d ? whht_b : whht_f;
    const float* bhh  = d ? bhh_b  : bhh_f;
    __shared__ __align__(16) float h_s[DIM];
    __shared__ float gh_s[G3];
    int tid = threadIdx.x;
    if (tid < DIM) h_s[tid] = 0.f;
    float bh = (tid < G3) ? bhh[tid] : 0.f;
    const float* wcol = whht + tid * 2;
    __syncthreads();
    for (int s = 0; s < len; s++) {
        int t = d ? (len - 1 - s) : s;
        if (tid < G3) {
            const ull* h2 = (const ull*)h_s;
            ull a0 = 0ull, a1 = 0ull, a2 = 0ull, a3 = 0ull;
            #pragma unroll 5
            for (int p = 0; p < DIM / 2; p += 4) {
                ffma2(a0, h2[p + 0], *(const ull*)(wcol + (size_t)(p + 0) * (2 * G3)));
                ffma2(a1, h2[p + 1], *(const ull*)(wcol + (size_t)(p + 1) * (2 * G3)));
                ffma2(a2, h2[p + 2], *(const ull*)(wcol + (size_t)(p + 2) * (2 * G3)));
                ffma2(a3, h2[p + 3], *(const ull*)(wcol + (size_t)(p + 3) * (2 * G3)));
            }
            gh_s[tid] = bh + lo32(a0) + hi32(a0) + lo32(a1) + hi32(a1)
                           + lo32(a2) + hi32(a2) + lo32(a3) + hi32(a3);
        }
        __syncthreads();
        if (tid < DIM) {
            const float* g = gx + (size_t)t * G3;
            float r = 1.f / (1.f + expf(-(g[tid]           + gh_s[tid])));
            float z = 1.f / (1.f + expf(-(g[DIM + tid]     + gh_s[DIM + tid])));
            float n = tanhf(g[2 * DIM + tid] + r * gh_s[2 * DIM + tid]);
            float hn = (1.f - z) * n + z * h_s[tid];
            h_s[tid] = hn;
            xout[(size_t)t * (2 * DIM) + tid] = hn;
        }
        __syncthreads();
    }
}

// ---------------- launcher ----------------
static inline int ceildiv(int a, int b) { return (a + b - 1) / b; }

extern "C" void kernel_launch(void* const* d_in, const int* in_sizes, int n_in,
                              void* d_out, int out_size) {
    (void)in_sizes; (void)n_in; (void)out_size;
    const int*   in_ab   = (const int*)d_in[0];
    const int*   in_ti   = (const int*)d_in[1];
    const int*   ab_len  = (const int*)d_in[2];
    const int*   ti_len  = (const int*)d_in[3];
    const int*   esrc    = (const int*)d_in[4];
    const int*   edst    = (const int*)d_in[5];
    const float* gnf     = (const float*)d_in[6];
    const float* emb     = (const float*)d_in[7];
    const float* wih_l0f = (const float*)d_in[8];
    const float* whh_l0f = (const float*)d_in[9];
    const float* bih_l0f = (const float*)d_in[10];
    const float* bhh_l0f = (const float*)d_in[11];
    const float* wih_l0b = (const float*)d_in[12];
    const float* whh_l0b = (const float*)d_in[13];
    const float* bih_l0b = (const float*)d_in[14];
    const float* bhh_l0b = (const float*)d_in[15];
    const float* wih_l1f = (const float*)d_in[16];
    const float* whh_l1f = (const float*)d_in[17];
    const float* bih_l1f = (const float*)d_in[18];
    const float* bhh_l1f = (const float*)d_in[19];
    const float* wih_l1b = (const float*)d_in[20];
    const float* whh_l1b = (const float*)d_in[21];
    const float* bih_l1b = (const float*)d_in[22];
    const float* bhh_l1b = (const float*)d_in[23];
    const float* gcn_w1  = (const float*)d_in[24];
    const float* gcn_b1  = (const float*)d_in[25];
    const float* gcn_w2  = (const float*)d_in[26];
    const float* gcn_b2  = (const float*)d_in[27];
    const float* fc1_w   = (const float*)d_in[28];
    const float* fc1_b   = (const float*)d_in[29];
    const float* fc2_w   = (const float*)d_in[30];
    const float* fc2_b   = (const float*)d_in[31];
    float* out = (float*)d_out;

    float* S = nullptr;  cudaGetSymbolAddress((void**)&S, SCR);
    bf16* Bb = nullptr;  cudaGetSymbolAddress((void**)&Bb, BSCR);
    float* AGG  = S + OFF_AGG;
    float* HB   = S + OFF_HB;
    float* LF   = S + OFF_LF;
    float* X0T  = S + OFF_X0T;
    float* X0A  = S + OFF_X0A;
    float* XL0T = S + OFF_XL0T;
    float* XL0A = S + OFF_XL0A;
    float* XL1T = S + OFF_XL1T;
    float* XL1A = S + OFF_XL1A;
    float* GX   = S + OFF_GX;
    float* WHHT = S + OFF_WHHT;
    float* LOG  = S + OFF_LOG;
    float* FEAT = S + OFF_FEAT;
    float* Y1   = S + OFF_Y1;

    cudaMemsetAsync(AGG,  0, SZ_AGG  * 4);
    cudaMemsetAsync(XL0T, 0, SZ_XL0T * 4);
    cudaMemsetAsync(XL0A, 0, SZ_XL0A * 4);
    cudaMemsetAsync(XL1T, 0, SZ_XL0T * 4);
    cudaMemsetAsync(XL1A, 0, SZ_XL0A * 4);

    {
        int blks = ceildiv(G3 * DIM, 256);
        pack_whh<<<blks, 256>>>(whh_l0f, WHHT + 0 * (size_t)DIM * G3);
        pack_whh<<<blks, 256>>>(whh_l0b, WHHT + 1 * (size_t)DIM * G3);
        pack_whh<<<blks, 256>>>(whh_l1f, WHHT + 2 * (size_t)DIM * G3);
        pack_whh<<<blks, 256>>>(whh_l1b, WHHT + 3 * (size_t)DIM * G3);
    }
    gather_emb<<<ceildiv(BATCH * T_TI * DIM, 256), 256>>>(in_ti, emb, X0T, BATCH * T_TI * DIM);
    gather_emb<<<ceildiv(BATCH * T_AB * DIM, 256), 256>>>(in_ab, emb, X0A, BATCH * T_AB * DIM);
    f2b2_pad<<<ceildiv(200 * KP, 256), 256>>>(fc1_w, Bb + B_FWH, Bb + B_FWL, 200, 400, KP);

    // ---- GCN ----
    {
        long total = (long)NEDGES * (DIM / 4);
        int blks = (int)((total + 255) / 256);
        gcn_agg<<<blks, 256>>>(gnf, esrc, edst, AGG);
        dim3 g1(ceildiv(DIM, 128), ceildiv(NL, 128), 1);
        gemm_nt128<<<g1, 256>>>(AGG, gcn_w1, gcn_b1, HB, NL, DIM, DIM, DIM, 1);
        cudaMemsetAsync(AGG, 0, SZ_AGG * 4);
        gcn_agg<<<blks, 256>>>(HB, esrc, edst, AGG);
        gemm_nt128<<<g1, 256>>>(AGG, gcn_w2, gcn_b2, LF, NL, DIM, DIM, 2 * DIM, 0);
        copy_to_lf<<<ceildiv(NL * DIM, 256), 256>>>(gnf, LF);
        f2b2_pad<<<(int)(((long)NL * KP + 255) / 256), 256>>>(LF, Bb + B_LFH, Bb + B_LFL, NL, 400, KP);
    }

    // ---- GRU layer 0 ----
    {
        dim3 gT(ceildiv(G3, 128), ceildiv(BATCH * T_TI, 128), 1);
        dim3 gA(ceildiv(G3, 128), ceildiv(BATCH * T_AB, 128), 1);
        gemm_nt128<<<gT, 256>>>(X0T, wih_l0f, bih_l0f, GX + 0 * GXS, BATCH * T_TI, G3, DIM, G3, 0);
        gemm_nt128<<<gT, 256>>>(X0T, wih_l0b, bih_l0b, GX + 1 * GXS, BATCH * T_TI, G3, DIM, G3, 0);
        gemm_nt128<<<gA, 256>>>(X0A, wih_l0f, bih_l0f, GX + 2 * GXS, BATCH * T_AB, G3, DIM, G3, 0);
        gemm_nt128<<<gA, 256>>>(X0A, wih_l0b, bih_l0b, GX + 3 * GXS, BATCH * T_AB, G3, DIM, G3, 0);
        dim3 gs(BATCH, 2, 2);
        gru_scan<<<gs, 640>>>(GX, WHHT + 0 * (size_t)DIM * G3, WHHT + 1 * (size_t)DIM * G3,
                              bhh_l0f, bhh_l0b, ti_len, ab_len, XL0T, XL0A);
    }
    // ---- GRU layer 1 ----
    {
        dim3 gT(ceildiv(G3, 128), ceildiv(BATCH * T_TI, 128), 1);
        dim3 gA(ceildiv(G3, 128), ceildiv(BATCH * T_AB, 128), 1);
        gemm_nt128<<<gT, 256>>>(XL0T, wih_l1f, bih_l1f, GX + 0 * GXS, BATCH * T_TI, G3, 2 * DIM, G3, 0);
        gemm_nt128<<<gT, 256>>>(XL0T, wih_l1b, bih_l1b, GX + 1 * GXS, BATCH * T_TI, G3, 2 * DIM, G3, 0);
        gemm_nt128<<<gA, 256>>>(XL0A, wih_l1f, bih_l1f, GX + 2 * GXS, BATCH * T_AB, G3, 2 * DIM, G3, 0);
        gemm_nt128<<<gA, 256>>>(XL0A, wih_l1b, bih_l1b, GX + 3 * GXS, BATCH * T_AB, G3, 2 * DIM, G3, 0);
        dim3 gs(BATCH, 2, 2);
        gru_scan<<<gs, 640>>>(GX, WHHT + 2 * (size_t)DIM * G3, WHHT + 3 * (size_t)DIM * G3,
                              bhh_l1f, bhh_l1b, ti_len, ab_len, XL1T, XL1A);
    }

    // ---- bf16 conversions ----
    f2b2_pad<<<ceildiv(BATCH * T_TI * KP, 256), 256>>>(XL1T, Bb + B_XTIH, Bb + B_XTIL,
                                                        BATCH * T_TI, 400, KP);
    f2b2_pad<<<ceildiv(BATCH * T_AB * KP, 256), 256>>>(XL1A, Bb + B_XAIH, Bb + B_XAIL,
                                                        BATCH * T_AB, 400, KP);
    build_xtc<<<ceildiv(BATCH * 400 * T_TI, 256), 256>>>(XL1T, Bb + B_XCH, Bb + B_XCL, T_TI, 0);
    build_xtc<<<ceildiv(BATCH * 400 * T_AB, 256), 256>>>(XL1A, Bb + B_XCH, Bb + B_XCL, T_AB, T_TI);

    int gy = ceildiv(NL, 128);
    // ---- logits + softmax: title then abstract, probs into fused P [b][n][448] ----
    {
        dim3 glt(1, gy, BATCH);
        wmma_nt<<<glt, 256>>>(Bb + B_LFH, Bb + B_LFL, Bb + B_XTIH, Bb + B_XTIL, LOG,
                              NL, T_TI, KP, KP, KP, T_TI, T_TI,
                              0, (size_t)T_TI * KP, (size_t)NL * T_TI, 0);
        softmax_pb<<<ceildiv(BATCH * NL, 8), 256>>>(LOG, Bb + B_PH, Bb + B_PL, BATCH * NL, T_TI, 0);
        dim3 gla(ceildiv(T_AB, 128), gy, BATCH);
        wmma_nt<<<gla, 256>>>(Bb + B_LFH, Bb + B_LFL, Bb + B_XAIH, Bb + B_XAIL, LOG,
                              NL, T_AB, KP, KP, KP, T_AB, T_AB,
                              0, (size_t)T_AB * KP, (size_t)NL * T_AB, 0);
        softmax_pb<<<ceildiv(BATCH * NL, 8), 256>>>(LOG, Bb + B_PH, Bb + B_PL, BATCH * NL, T_AB, T_TI);
    }
    // ---- fused weighted sum: FEAT = P[NL x 448] * XC[400 x 448]^T ----
    {
        dim3 gw(ceildiv(400, 128), gy, BATCH);
        wmma_nt<<<gw, 256>>>(Bb + B_PH, Bb + B_PL, Bb + B_XCH, Bb + B_XCL, FEAT,
                             NL, 400, KC, KC, KC, 400, 400,
                             (size_t)NL * KC, (size_t)400 * KC, (size_t)NL * 400, 0);
    }

    // ---- output head ----
    {
        f2b2_pad<<<(int)(((long)BATCH * NL * KP + 255) / 256), 256>>>(
            FEAT, Bb + B_FH, Bb + B_FL, (long)BATCH * NL, 400, KP);
        dim3 gf(2, ceildiv(BATCH * NL, 128), 1);
        wmma_nt<<<gf, 256>>>(Bb + B_FH, Bb + B_FL, Bb + B_FWH, Bb + B_FWL, Y1,
                             BATCH * NL, Y1LD, KP, KP, KP, 200, Y1LD,
                             0, 0, 0, 0);
        bias_leaky<<<(int)(((long)BATCH * NL * 200 + 255) / 256), 256>>>(Y1, fc1_b, (long)BATCH * NL);
        fc2_kernel<<<ceildiv(BATCH * NL, 8), 256>>>(Y1, fc2_w, fc2_b, out, BATCH * NL);
    }
}